// round 1
// baseline (speedup 1.0000x reference)
#include <cuda_runtime.h>
#include <cstdint>
#include <cstddef>

// Problem constants
#define B_     4
#define N_     2048
#define QD     1024
#define H_     16
#define DH     64
#define INNER_ 1024
#define BH     (B_ * H_)     // 64
#define ROWS   (B_ * N_)     // 8192

// Scratch (allocation-free: __device__ globals)
__device__ float g_q[(size_t)BH * N_ * DH];       // 33.5 MB
__device__ float g_k[(size_t)BH * N_ * DH];
__device__ float g_v[(size_t)BH * N_ * DH];
__device__ float g_S[(size_t)BH * N_ * N_];       // 1.07 GB
__device__ float g_att[(size_t)ROWS * INNER_];    // 33.5 MB

// ----------------------------------------------------------------------------
// Kernel 1: fused QKV projection.  C = x @ W{q,k,v}; epilogue scatters into
// [B,H,N,DH] layout.  Classic 128x128x16 register-tiled SGEMM, 256 threads,
// 8x8 per-thread micro-tile.
// ----------------------------------------------------------------------------
__global__ __launch_bounds__(256) void qkv_kernel(
    const float* __restrict__ x,
    const float* __restrict__ Wq,
    const float* __restrict__ Wk,
    const float* __restrict__ Wv)
{
    const float* W   = (blockIdx.z == 0) ? Wq : (blockIdx.z == 1) ? Wk : Wv;
    float*       dst = (blockIdx.z == 0) ? g_q : (blockIdx.z == 1) ? g_k : g_v;

    __shared__ float As[16][128];
    __shared__ float Bs[16][128];

    const int tid  = threadIdx.x;
    const int row0 = blockIdx.y * 128;
    const int col0 = blockIdx.x * 128;

    const int aRow = tid >> 2;          // 0..63  (2 passes of 64 rows)
    const int aCol = (tid & 3) * 4;     // 0,4,8,12
    const int bRow = tid >> 5;          // 0..7   (2 passes of 8 rows)
    const int bCol = (tid & 31) * 4;    // 0..124
    const int tr   = (tid >> 4) * 8;
    const int tc   = (tid & 15) * 8;

    float acc[8][8] = {};

    for (int k0 = 0; k0 < QD; k0 += 16) {
        #pragma unroll
        for (int m = 0; m < 128; m += 64) {
            float4 a = *(const float4*)(x + (size_t)(row0 + aRow + m) * QD + k0 + aCol);
            As[aCol + 0][aRow + m] = a.x;
            As[aCol + 1][aRow + m] = a.y;
            As[aCol + 2][aRow + m] = a.z;
            As[aCol + 3][aRow + m] = a.w;
        }
        #pragma unroll
        for (int r = 0; r < 16; r += 8) {
            float4 bv = *(const float4*)(W + (size_t)(k0 + bRow + r) * INNER_ + col0 + bCol);
            *(float4*)(&Bs[bRow + r][bCol]) = bv;
        }
        __syncthreads();

        #pragma unroll
        for (int k = 0; k < 16; k++) {
            float rm[8], rn[8];
            #pragma unroll
            for (int i = 0; i < 8; i++) rm[i] = As[k][tr + i];
            #pragma unroll
            for (int j = 0; j < 8; j++) rn[j] = Bs[k][tc + j];
            #pragma unroll
            for (int i = 0; i < 8; i++)
                #pragma unroll
                for (int j = 0; j < 8; j++)
                    acc[i][j] += rm[i] * rn[j];
        }
        __syncthreads();
    }

    // Epilogue: scatter to [B,H,N,DH]
    #pragma unroll
    for (int i = 0; i < 8; i++) {
        int m = row0 + tr + i;
        int b = m >> 11;            // /2048
        int n = m & (N_ - 1);
        #pragma unroll
        for (int j = 0; j < 8; j++) {
            int c = col0 + tc + j;
            int h = c >> 6;
            int d = c & 63;
            dst[(((size_t)(b * H_ + h)) * N_ + n) * DH + d] = acc[i][j];
        }
    }
}

// ----------------------------------------------------------------------------
// Kernel 2: S = scale * Q @ K^T per (b,h) slice, masked in epilogue.
// ----------------------------------------------------------------------------
__global__ __launch_bounds__(256) void scores_kernel(const int* __restrict__ masks)
{
    const int z = blockIdx.z;          // b*H + h
    const int b = z >> 4;
    const float* Q = g_q + (size_t)z * N_ * DH;
    const float* K = g_k + (size_t)z * N_ * DH;

    __shared__ float As[16][128];
    __shared__ float Bs[16][128];

    const int tid  = threadIdx.x;
    const int row0 = blockIdx.y * 128;
    const int col0 = blockIdx.x * 128;

    const int aRow = tid >> 2;
    const int aCol = (tid & 3) * 4;
    const int tr   = (tid >> 4) * 8;
    const int tc   = (tid & 15) * 8;

    float acc[8][8] = {};

    for (int k0 = 0; k0 < DH; k0 += 16) {
        #pragma unroll
        for (int m = 0; m < 128; m += 64) {
            float4 a = *(const float4*)(Q + (size_t)(row0 + aRow + m) * DH + k0 + aCol);
            As[aCol + 0][aRow + m] = a.x;
            As[aCol + 1][aRow + m] = a.y;
            As[aCol + 2][aRow + m] = a.z;
            As[aCol + 3][aRow + m] = a.w;
            float4 bv = *(const float4*)(K + (size_t)(col0 + aRow + m) * DH + k0 + aCol);
            Bs[aCol + 0][aRow + m] = bv.x;
            Bs[aCol + 1][aRow + m] = bv.y;
            Bs[aCol + 2][aRow + m] = bv.z;
            Bs[aCol + 3][aRow + m] = bv.w;
        }
        __syncthreads();

        #pragma unroll
        for (int k = 0; k < 16; k++) {
            float rm[8], rn[8];
            #pragma unroll
            for (int i = 0; i < 8; i++) rm[i] = As[k][tr + i];
            #pragma unroll
            for (int j = 0; j < 8; j++) rn[j] = Bs[k][tc + j];
            #pragma unroll
            for (int i = 0; i < 8; i++)
                #pragma unroll
                for (int j = 0; j < 8; j++)
                    acc[i][j] += rm[i] * rn[j];
        }
        __syncthreads();
    }

    const float scale = 0.125f;   // 1/sqrt(64)
    #pragma unroll
    for (int i = 0; i < 8; i++) {
        int ig = row0 + tr + i;
        #pragma unroll
        for (int j = 0; j < 8; j++) {
            int jg = col0 + tc + j;
            float s = acc[i][j] * scale;
            int mv = masks[((size_t)b * N_ + ig) * N_ + jg];
            if (mv <= 0) s = -1e30f;
            g_S[((size_t)z * N_ + ig) * N_ + jg] = s;
        }
    }
}

// ----------------------------------------------------------------------------
// Kernel 3: row softmax over g_S (one block per row; row cached in smem).
// ----------------------------------------------------------------------------
__global__ __launch_bounds__(256) void softmax_kernel()
{
    __shared__ float buf[N_];
    __shared__ float red[256];

    const size_t base = (size_t)blockIdx.x * N_;
    const int tid = threadIdx.x;

    float m = -1e30f;
    for (int j = tid; j < N_; j += 256) {
        float v = g_S[base + j];
        buf[j] = v;
        m = fmaxf(m, v);
    }
    red[tid] = m;
    __syncthreads();
    for (int s = 128; s > 0; s >>= 1) {
        if (tid < s) red[tid] = fmaxf(red[tid], red[tid + s]);
        __syncthreads();
    }
    const float rmax = red[0];
    __syncthreads();

    float sum = 0.f;
    for (int j = tid; j < N_; j += 256) {
        float e = __expf(buf[j] - rmax);
        buf[j] = e;
        sum += e;
    }
    red[tid] = sum;
    __syncthreads();
    for (int s = 128; s > 0; s >>= 1) {
        if (tid < s) red[tid] += red[tid + s];
        __syncthreads();
    }
    const float inv = 1.f / red[0];

    for (int j = tid; j < N_; j += 256)
        g_S[base + j] = buf[j] * inv;
}

// ----------------------------------------------------------------------------
// Kernel 4: O = P @ V per (b,h) slice.  128x64 tile, 8x4 per-thread micro-tile.
// Epilogue writes [B,N,INNER] layout for the output projection.
// ----------------------------------------------------------------------------
__global__ __launch_bounds__(256) void pv_kernel()
{
    const int z = blockIdx.z;
    const int b = z >> 4;
    const int h = z & 15;
    const float* P = g_S + (size_t)z * N_ * N_;
    const float* V = g_v + (size_t)z * N_ * DH;

    __shared__ float As[16][128];
    __shared__ float Bs[16][64];

    const int tid  = threadIdx.x;
    const int row0 = blockIdx.y * 128;

    const int aRow = tid >> 2;
    const int aCol = (tid & 3) * 4;
    const int bRow = tid >> 4;          // 0..15 (single pass)
    const int bCol = (tid & 15) * 4;    // 0..60
    const int tr   = (tid >> 4) * 8;
    const int tc   = (tid & 15) * 4;

    float acc[8][4] = {};

    for (int k0 = 0; k0 < N_; k0 += 16) {
        #pragma unroll
        for (int m = 0; m < 128; m += 64) {
            float4 a = *(const float4*)(P + (size_t)(row0 + aRow + m) * N_ + k0 + aCol);
            As[aCol + 0][aRow + m] = a.x;
            As[aCol + 1][aRow + m] = a.y;
            As[aCol + 2][aRow + m] = a.z;
            As[aCol + 3][aRow + m] = a.w;
        }
        {
            float4 bv = *(const float4*)(V + (size_t)(k0 + bRow) * DH + bCol);
            *(float4*)(&Bs[bRow][bCol]) = bv;
        }
        __syncthreads();

        #pragma unroll
        for (int k = 0; k < 16; k++) {
            float rm[8], rn[4];
            #pragma unroll
            for (int i = 0; i < 8; i++) rm[i] = As[k][tr + i];
            #pragma unroll
            for (int j = 0; j < 4; j++) rn[j] = Bs[k][tc + j];
            #pragma unroll
            for (int i = 0; i < 8; i++)
                #pragma unroll
                for (int j = 0; j < 4; j++)
                    acc[i][j] += rm[i] * rn[j];
        }
        __syncthreads();
    }

    #pragma unroll
    for (int i = 0; i < 8; i++) {
        int ig = row0 + tr + i;
        #pragma unroll
        for (int j = 0; j < 4; j++) {
            int d = tc + j;
            g_att[((size_t)(b * N_ + ig)) * INNER_ + h * DH + d] = acc[i][j];
        }
    }
}

// ----------------------------------------------------------------------------
// Kernel 5: out = g_att @ Wo + bo  ->  d_out
// ----------------------------------------------------------------------------
__global__ __launch_bounds__(256) void outproj_kernel(
    const float* __restrict__ Wo,
    const float* __restrict__ bo,
    float* __restrict__ out)
{
    __shared__ float As[16][128];
    __shared__ float Bs[16][128];

    const int tid  = threadIdx.x;
    const int row0 = blockIdx.y * 128;
    const int col0 = blockIdx.x * 128;

    const int aRow = tid >> 2;
    const int aCol = (tid & 3) * 4;
    const int bRow = tid >> 5;
    const int bCol = (tid & 31) * 4;
    const int tr   = (tid >> 4) * 8;
    const int tc   = (tid & 15) * 8;

    float acc[8][8] = {};

    for (int k0 = 0; k0 < INNER_; k0 += 16) {
        #pragma unroll
        for (int m = 0; m < 128; m += 64) {
            float4 a = *(const float4*)(g_att + (size_t)(row0 + aRow + m) * INNER_ + k0 + aCol);
            As[aCol + 0][aRow + m] = a.x;
            As[aCol + 1][aRow + m] = a.y;
            As[aCol + 2][aRow + m] = a.z;
            As[aCol + 3][aRow + m] = a.w;
        }
        #pragma unroll
        for (int r = 0; r < 16; r += 8) {
            float4 bv = *(const float4*)(Wo + (size_t)(k0 + bRow + r) * QD + col0 + bCol);
            *(float4*)(&Bs[bRow + r][bCol]) = bv;
        }
        __syncthreads();

        #pragma unroll
        for (int k = 0; k < 16; k++) {
            float rm[8], rn[8];
            #pragma unroll
            for (int i = 0; i < 8; i++) rm[i] = As[k][tr + i];
            #pragma unroll
            for (int j = 0; j < 8; j++) rn[j] = Bs[k][tc + j];
            #pragma unroll
            for (int i = 0; i < 8; i++)
                #pragma unroll
                for (int j = 0; j < 8; j++)
                    acc[i][j] += rm[i] * rn[j];
        }
        __syncthreads();
    }

    #pragma unroll
    for (int i = 0; i < 8; i++) {
        int m = row0 + tr + i;
        #pragma unroll
        for (int j = 0; j < 8; j++) {
            int c = col0 + tc + j;
            out[(size_t)m * QD + c] = acc[i][j] + bo[c];
        }
    }
}

// ----------------------------------------------------------------------------
// Launch
// ----------------------------------------------------------------------------
extern "C" void kernel_launch(void* const* d_in, const int* in_sizes, int n_in,
                              void* d_out, int out_size)
{
    const float* x     = (const float*)d_in[0];
    const int*   masks = (const int*)  d_in[1];
    const float* Wq    = (const float*)d_in[2];
    const float* Wk    = (const float*)d_in[3];
    const float* Wv    = (const float*)d_in[4];
    const float* Wo    = (const float*)d_in[5];
    const float* bo    = (const float*)d_in[6];
    float* out = (float*)d_out;

    (void)in_sizes; (void)n_in; (void)out_size;

    // 1) QKV projections: [8192,1024] @ [1024,1024] x3
    qkv_kernel<<<dim3(INNER_ / 128, ROWS / 128, 3), 256>>>(x, Wq, Wk, Wv);

    // 2) Masked scaled scores per (b,h)
    scores_kernel<<<dim3(N_ / 128, N_ / 128, BH), 256>>>(masks);

    // 3) Row softmax
    softmax_kernel<<<BH * N_, 256>>>();

    // 4) O = P @ V
    pv_kernel<<<dim3(1, N_ / 128, BH), 256>>>();

    // 5) Output projection + bias
    outproj_kernel<<<dim3(QD / 128, ROWS / 128), 256>>>(Wo, bo, out);
}

// round 3
// speedup vs baseline: 1.8135x; 1.8135x over previous
#include <cuda_runtime.h>
#include <cuda_bf16.h>
#include <cstdint>
#include <cstddef>

// ---------------------------------------------------------------------------
// Problem constants
// ---------------------------------------------------------------------------
#define B_     4
#define N_     2048
#define QD     1024
#define H_     16
#define DH     64
#define INNER_ 1024
#define BH     (B_ * H_)     // 64
#define ROWS   (B_ * N_)     // 8192

// ---------------------------------------------------------------------------
// Device scratch (allocation-free)
// ---------------------------------------------------------------------------
__device__ __nv_bfloat16 g_xh[(size_t)ROWS * QD];
__device__ __nv_bfloat16 g_xl[(size_t)ROWS * QD];
__device__ __nv_bfloat16 g_wth[(size_t)4 * QD * INNER_];   // [slot][n][k]
__device__ __nv_bfloat16 g_wtl[(size_t)4 * QD * INNER_];
__device__ __nv_bfloat16 g_qh[(size_t)BH * N_ * DH];
__device__ __nv_bfloat16 g_ql[(size_t)BH * N_ * DH];
__device__ __nv_bfloat16 g_kh[(size_t)BH * N_ * DH];
__device__ __nv_bfloat16 g_kl[(size_t)BH * N_ * DH];
__device__ __nv_bfloat16 g_vth[(size_t)BH * DH * N_];      // [bh][d][n]
__device__ __nv_bfloat16 g_vtl[(size_t)BH * DH * N_];
__device__ __nv_bfloat16 g_Eh[(size_t)BH * N_ * N_];       // exp(masked scores)
__device__ __nv_bfloat16 g_El[(size_t)BH * N_ * N_];
__device__ float         g_psum[(size_t)BH * N_ * 16];     // partial row sums
__device__ __nv_bfloat16 g_ath[(size_t)ROWS * INNER_];
__device__ __nv_bfloat16 g_atl[(size_t)ROWS * INNER_];
__device__ uint32_t      g_mb[(size_t)B_ * N_ * (N_ / 32)];

// ---------------------------------------------------------------------------
// Helpers
// ---------------------------------------------------------------------------
__device__ __forceinline__ uint32_t smem_to_u32(const void* p) {
    uint32_t a;
    asm("{ .reg .u64 t; cvta.to.shared.u64 t, %1; cvt.u32.u64 %0, t; }"
        : "=r"(a) : "l"(p));
    return a;
}

__device__ __forceinline__ void bsplit(float f, __nv_bfloat16& h, __nv_bfloat16& l) {
    h = __float2bfloat16(f);
    l = __float2bfloat16(f - __bfloat162float(h));
}

__device__ __forceinline__ void ldm_x4(uint32_t (&r)[4], uint32_t base, int row0,
                                       int ch0, int lane) {
    int m   = lane >> 3;
    int row = row0 + ((m & 1) << 3) + (lane & 7);
    int ch  = ch0 + (m >> 1);
    uint32_t addr = base + row * 80 + ch * 16;
    asm volatile("ldmatrix.sync.aligned.m8n8.x4.shared.b16 {%0,%1,%2,%3}, [%4];"
                 : "=r"(r[0]), "=r"(r[1]), "=r"(r[2]), "=r"(r[3]) : "r"(addr));
}

__device__ __forceinline__ void mma_bf16(float (&d)[4], const uint32_t (&a)[4],
                                         uint32_t b0, uint32_t b1) {
    asm volatile(
        "mma.sync.aligned.m16n8k16.row.col.f32.bf16.bf16.f32 "
        "{%0,%1,%2,%3}, {%4,%5,%6,%7}, {%8,%9}, {%0,%1,%2,%3};"
        : "+f"(d[0]), "+f"(d[1]), "+f"(d[2]), "+f"(d[3])
        : "r"(a[0]), "r"(a[1]), "r"(a[2]), "r"(a[3]), "r"(b0), "r"(b1));
}

// Load a R x 32(bf16) tile into smem with 80B row pitch (conflict-free ldmatrix).
template <int R>
__device__ __forceinline__ void load_tile(char* st, const __nv_bfloat16* g,
                                          size_t ld, int tid) {
    for (int i = tid; i < R * 4; i += 256) {
        int r = i >> 2, c = i & 3;
        *(uint4*)(st + r * 80 + c * 16) = *((const uint4*)(g + (size_t)r * ld) + c);
    }
}

// One BK=32 chunk of the hi/lo-compensated bf16 MMA (3 products).
template <int MI, int NI>
__device__ __forceinline__ void mma_tiles(
    float (&acc)[MI][NI][4],
    uint32_t sAh, uint32_t sAl, uint32_t sBh, uint32_t sBl,
    int wm0, int wn0, int lane)
{
#pragma unroll
    for (int ks = 0; ks < 2; ks++) {
        uint32_t ah[MI][4], al[MI][4];
#pragma unroll
        for (int mi = 0; mi < MI; mi++) {
            ldm_x4(ah[mi], sAh, wm0 + mi * 16, ks * 2, lane);
            ldm_x4(al[mi], sAl, wm0 + mi * 16, ks * 2, lane);
        }
#pragma unroll
        for (int nj = 0; nj < NI / 2; nj++) {
            uint32_t bh[4], bl[4];
            ldm_x4(bh, sBh, wn0 + nj * 16, ks * 2, lane);
            ldm_x4(bl, sBl, wn0 + nj * 16, ks * 2, lane);
#pragma unroll
            for (int mi = 0; mi < MI; mi++) {
                mma_bf16(acc[mi][nj * 2],     ah[mi], bh[0], bh[2]);
                mma_bf16(acc[mi][nj * 2],     al[mi], bh[0], bh[2]);
                mma_bf16(acc[mi][nj * 2],     ah[mi], bl[0], bl[2]);
                mma_bf16(acc[mi][nj * 2 + 1], ah[mi], bh[1], bh[3]);
                mma_bf16(acc[mi][nj * 2 + 1], al[mi], bh[1], bh[3]);
                mma_bf16(acc[mi][nj * 2 + 1], ah[mi], bl[1], bl[3]);
            }
        }
    }
}

// ---------------------------------------------------------------------------
// Preprocessing kernels
// ---------------------------------------------------------------------------
__global__ __launch_bounds__(256) void conv_x_kernel(const float* __restrict__ x)
{
    size_t i = ((size_t)blockIdx.x * 256 + threadIdx.x) * 8;
    float4 a = *(const float4*)(x + i);
    float4 b = *(const float4*)(x + i + 4);
    float v[8] = {a.x, a.y, a.z, a.w, b.x, b.y, b.z, b.w};
    __align__(16) __nv_bfloat16 h[8], l[8];
#pragma unroll
    for (int j = 0; j < 8; j++) bsplit(v[j], h[j], l[j]);
    *(uint4*)(g_xh + i) = *(uint4*)h;
    *(uint4*)(g_xl + i) = *(uint4*)l;
}

__global__ __launch_bounds__(256) void w_trans_kernel(
    const float* __restrict__ Wq, const float* __restrict__ Wk,
    const float* __restrict__ Wv, const float* __restrict__ Wo)
{
    const float* W = (blockIdx.z == 0) ? Wq : (blockIdx.z == 1) ? Wk
                   : (blockIdx.z == 2) ? Wv : Wo;
    __shared__ float t[32][33];
    int tx = threadIdx.x, ty = threadIdx.y;      // (32, 8)
    int n0 = blockIdx.x * 32, k0 = blockIdx.y * 32;
#pragma unroll
    for (int i = 0; i < 32; i += 8)
        t[ty + i][tx] = W[(size_t)(k0 + ty + i) * INNER_ + n0 + tx];
    __syncthreads();
    __nv_bfloat16* wh = g_wth + (size_t)blockIdx.z * QD * INNER_;
    __nv_bfloat16* wl = g_wtl + (size_t)blockIdx.z * QD * INNER_;
#pragma unroll
    for (int i = 0; i < 32; i += 8) {
        int n = n0 + ty + i, k = k0 + tx;
        __nv_bfloat16 h, l;
        bsplit(t[tx][ty + i], h, l);
        wh[(size_t)n * QD + k] = h;
        wl[(size_t)n * QD + k] = l;
    }
}

__global__ __launch_bounds__(256) void mask_pack_kernel(const int* __restrict__ m)
{
    size_t w = (size_t)blockIdx.x * 256 + threadIdx.x;
    const int* src = m + w * 32;
    uint32_t bits = 0;
#pragma unroll
    for (int j = 0; j < 32; j++) bits |= (uint32_t)(src[j] > 0) << j;
    g_mb[w] = bits;
}

// ---------------------------------------------------------------------------
// Kernel A: QKV projection.  BM=BN=128, BK=32, 8 warps (2x4), warp 64x32.
// ---------------------------------------------------------------------------
__global__ __launch_bounds__(256, 2) void qkv_hmma()
{
    __shared__ __align__(16) char sAh[128 * 80], sAl[128 * 80];
    __shared__ __align__(16) char sBh[128 * 80], sBl[128 * 80];

    const int tid = threadIdx.x, lane = tid & 31, w = tid >> 5;
    const int wm0 = (w >> 2) * 64, wn0 = (w & 3) * 32;
    const int z = blockIdx.z;
    const int row0 = blockIdx.y * 128, col0 = blockIdx.x * 128;

    const __nv_bfloat16* wh = g_wth + (size_t)z * QD * INNER_;
    const __nv_bfloat16* wl = g_wtl + (size_t)z * QD * INNER_;

    const uint32_t uAh = smem_to_u32(sAh), uAl = smem_to_u32(sAl);
    const uint32_t uBh = smem_to_u32(sBh), uBl = smem_to_u32(sBl);

    float acc[4][4][4] = {};

    for (int k0 = 0; k0 < QD; k0 += 32) {
        load_tile<128>(sAh, g_xh + (size_t)row0 * QD + k0, QD, tid);
        load_tile<128>(sAl, g_xl + (size_t)row0 * QD + k0, QD, tid);
        load_tile<128>(sBh, wh + (size_t)col0 * QD + k0, QD, tid);
        load_tile<128>(sBl, wl + (size_t)col0 * QD + k0, QD, tid);
        __syncthreads();
        mma_tiles<4, 4>(acc, uAh, uAl, uBh, uBl, wm0, wn0, lane);
        __syncthreads();
    }

    if (z < 2) {
        __nv_bfloat16* dh_ = (z == 0) ? g_qh : g_kh;
        __nv_bfloat16* dl_ = (z == 0) ? g_ql : g_kl;
#pragma unroll
        for (int mi = 0; mi < 4; mi++)
#pragma unroll
            for (int h2 = 0; h2 < 2; h2++) {
                int m = row0 + wm0 + mi * 16 + (lane >> 2) + h2 * 8;
                int b = m >> 11, n = m & (N_ - 1);
#pragma unroll
                for (int ni = 0; ni < 4; ni++) {
                    int c = col0 + wn0 + ni * 8 + 2 * (lane & 3);
                    int hh = c >> 6, dd = c & 63;
                    __nv_bfloat16 h0, l0, h1, l1;
                    bsplit(acc[mi][ni][h2 * 2 + 0], h0, l0);
                    bsplit(acc[mi][ni][h2 * 2 + 1], h1, l1);
                    size_t off = ((size_t)(b * H_ + hh) * N_ + n) * DH + dd;
                    __nv_bfloat162 ph; ph.x = h0; ph.y = h1;
                    __nv_bfloat162 pl; pl.x = l0; pl.y = l1;
                    *(__nv_bfloat162*)(dh_ + off) = ph;
                    *(__nv_bfloat162*)(dl_ + off) = pl;
                }
            }
    } else {
        // V: write transposed [bh][d][n]
#pragma unroll
        for (int mi = 0; mi < 4; mi++)
#pragma unroll
            for (int h2 = 0; h2 < 2; h2++) {
                int m = row0 + wm0 + mi * 16 + (lane >> 2) + h2 * 8;
                int b = m >> 11, n = m & (N_ - 1);
#pragma unroll
                for (int ni = 0; ni < 4; ni++)
#pragma unroll
                    for (int c01 = 0; c01 < 2; c01++) {
                        int c = col0 + wn0 + ni * 8 + 2 * (lane & 3) + c01;
                        int hh = c >> 6, dd = c & 63;
                        __nv_bfloat16 h, l;
                        bsplit(acc[mi][ni][h2 * 2 + c01], h, l);
                        size_t off = ((size_t)(b * H_ + hh) * DH + dd) * N_ + n;
                        g_vth[off] = h;
                        g_vtl[off] = l;
                    }
            }
    }
}

// ---------------------------------------------------------------------------
// Kernel B: scores + mask + exp.  Per (b,h): S tile 128x128, K=64.
// Writes E = exp(scale*QK^T) masked, bf16 hi/lo, plus partial row sums.
// ---------------------------------------------------------------------------
__global__ __launch_bounds__(256, 2) void scores_hmma()
{
    __shared__ __align__(16) char sAh[128 * 80], sAl[128 * 80];
    __shared__ __align__(16) char sBh[128 * 80], sBl[128 * 80];
    __shared__ float psum_s[128];

    const int tid = threadIdx.x, lane = tid & 31, w = tid >> 5;
    const int wm0 = (w >> 2) * 64, wn0 = (w & 3) * 32;
    const int z = blockIdx.z, b = z >> 4;
    const int row0 = blockIdx.y * 128, col0 = blockIdx.x * 128;

    if (tid < 128) psum_s[tid] = 0.f;

    const uint32_t uAh = smem_to_u32(sAh), uAl = smem_to_u32(sAl);
    const uint32_t uBh = smem_to_u32(sBh), uBl = smem_to_u32(sBl);

    const size_t qb = (size_t)z * N_ * DH;
    float acc[4][4][4] = {};

    for (int k0 = 0; k0 < DH; k0 += 32) {
        load_tile<128>(sAh, g_qh + qb + (size_t)row0 * DH + k0, DH, tid);
        load_tile<128>(sAl, g_ql + qb + (size_t)row0 * DH + k0, DH, tid);
        load_tile<128>(sBh, g_kh + qb + (size_t)col0 * DH + k0, DH, tid);
        load_tile<128>(sBl, g_kl + qb + (size_t)col0 * DH + k0, DH, tid);
        __syncthreads();
        mma_tiles<4, 4>(acc, uAh, uAl, uBh, uBl, wm0, wn0, lane);
        __syncthreads();
    }

    const int mword = (col0 + wn0) >> 5;
#pragma unroll
    for (int mi = 0; mi < 4; mi++)
#pragma unroll
        for (int h2 = 0; h2 < 2; h2++) {
            int rloc = wm0 + mi * 16 + (lane >> 2) + h2 * 8;
            int i = row0 + rloc;
            uint32_t mw = g_mb[((size_t)b * N_ + i) * (N_ / 32) + mword];
            size_t ebase = ((size_t)z * N_ + i) * N_;
            float rs = 0.f;
#pragma unroll
            for (int ni = 0; ni < 4; ni++) {
                int bit = ni * 8 + 2 * (lane & 3);
                float e0 = 0.f, e1 = 0.f;
                if ((mw >> bit) & 1u)
                    e0 = __expf(acc[mi][ni][h2 * 2 + 0] * 0.125f);
                if ((mw >> (bit + 1)) & 1u)
                    e1 = __expf(acc[mi][ni][h2 * 2 + 1] * 0.125f);
                rs += e0 + e1;
                __nv_bfloat16 h0, l0, h1, l1;
                bsplit(e0, h0, l0);
                bsplit(e1, h1, l1);
                size_t off = ebase + col0 + wn0 + ni * 8 + 2 * (lane & 3);
                __nv_bfloat162 ph; ph.x = h0; ph.y = h1;
                __nv_bfloat162 pl; pl.x = l0; pl.y = l1;
                *(__nv_bfloat162*)(g_Eh + off) = ph;
                *(__nv_bfloat162*)(g_El + off) = pl;
            }
            rs += __shfl_xor_sync(0xFFFFFFFF, rs, 1);
            rs += __shfl_xor_sync(0xFFFFFFFF, rs, 2);
            if ((lane & 3) == 0) atomicAdd(&psum_s[rloc], rs);
        }
    __syncthreads();
    if (tid < 128)
        g_psum[((size_t)z * N_ + row0 + tid) * 16 + blockIdx.x] = psum_s[tid];
}

// ---------------------------------------------------------------------------
// Kernel C: PV.  O[128x64] = (E/rowsum)[128x2048] @ V.  BM=128, BN=64,
// 8 warps (4x2), warp 32x32.
// ---------------------------------------------------------------------------
__global__ __launch_bounds__(256, 2) void pv_hmma()
{
    __shared__ __align__(16) char sAh[128 * 80], sAl[128 * 80];
    __shared__ __align__(16) char sBh[64 * 80], sBl[64 * 80];
    __shared__ float inv_s[128];

    const int tid = threadIdx.x, lane = tid & 31, w = tid >> 5;
    const int wm0 = (w >> 1) * 32, wn0 = (w & 1) * 32;
    const int z = blockIdx.z, b = z >> 4, hh = z & 15;
    const int row0 = blockIdx.y * 128;

    if (tid < 128) {
        const float* ps = g_psum + ((size_t)z * N_ + row0 + tid) * 16;
        float s = 0.f;
#pragma unroll
        for (int t = 0; t < 16; t++) s += ps[t];
        inv_s[tid] = 1.f / s;
    }

    const uint32_t uAh = smem_to_u32(sAh), uAl = smem_to_u32(sAl);
    const uint32_t uBh = smem_to_u32(sBh), uBl = smem_to_u32(sBl);

    const size_t eb = (size_t)z * N_ * N_;
    const size_t vb = (size_t)z * DH * N_;
    float acc[2][4][4] = {};

    for (int k0 = 0; k0 < N_; k0 += 32) {
        load_tile<128>(sAh, g_Eh + eb + (size_t)row0 * N_ + k0, N_, tid);
        load_tile<128>(sAl, g_El + eb + (size_t)row0 * N_ + k0, N_, tid);
        load_tile<64>(sBh, g_vth + vb + k0, N_, tid);
        load_tile<64>(sBl, g_vtl + vb + k0, N_, tid);
        __syncthreads();
        mma_tiles<2, 4>(acc, uAh, uAl, uBh, uBl, wm0, wn0, lane);
        __syncthreads();
    }

#pragma unroll
    for (int mi = 0; mi < 2; mi++)
#pragma unroll
        for (int h2 = 0; h2 < 2; h2++) {
            int rloc = wm0 + mi * 16 + (lane >> 2) + h2 * 8;
            int i = row0 + rloc;
            float inv = inv_s[rloc];
#pragma unroll
            for (int ni = 0; ni < 4; ni++) {
                int c = wn0 + ni * 8 + 2 * (lane & 3);
                __nv_bfloat16 h0, l0, h1, l1;
                bsplit(acc[mi][ni][h2 * 2 + 0] * inv, h0, l0);
                bsplit(acc[mi][ni][h2 * 2 + 1] * inv, h1, l1);
                size_t off = ((size_t)(b * N_ + i)) * INNER_ + hh * 64 + c;
                __nv_bfloat162 ph; ph.x = h0; ph.y = h1;
                __nv_bfloat162 pl; pl.x = l0; pl.y = l1;
                *(__nv_bfloat162*)(g_ath + off) = ph;
                *(__nv_bfloat162*)(g_atl + off) = pl;
            }
        }
}

// ---------------------------------------------------------------------------
// Kernel D: output projection + bias -> d_out (fp32).
// ---------------------------------------------------------------------------
__global__ __launch_bounds__(256, 2) void outproj_hmma(
    const float* __restrict__ bo, float* __restrict__ out)
{
    __shared__ __align__(16) char sAh[128 * 80], sAl[128 * 80];
    __shared__ __align__(16) char sBh[128 * 80], sBl[128 * 80];

    const int tid = threadIdx.x, lane = tid & 31, w = tid >> 5;
    const int wm0 = (w >> 2) * 64, wn0 = (w & 3) * 32;
    const int row0 = blockIdx.y * 128, col0 = blockIdx.x * 128;

    const __nv_bfloat16* wh = g_wth + (size_t)3 * QD * INNER_;
    const __nv_bfloat16* wl = g_wtl + (size_t)3 * QD * INNER_;

    const uint32_t uAh = smem_to_u32(sAh), uAl = smem_to_u32(sAl);
    const uint32_t uBh = smem_to_u32(sBh), uBl = smem_to_u32(sBl);

    float acc[4][4][4] = {};

    for (int k0 = 0; k0 < INNER_; k0 += 32) {
        load_tile<128>(sAh, g_ath + (size_t)row0 * INNER_ + k0, INNER_, tid);
        load_tile<128>(sAl, g_atl + (size_t)row0 * INNER_ + k0, INNER_, tid);
        load_tile<128>(sBh, wh + (size_t)col0 * QD + k0, QD, tid);
        load_tile<128>(sBl, wl + (size_t)col0 * QD + k0, QD, tid);
        __syncthreads();
        mma_tiles<4, 4>(acc, uAh, uAl, uBh, uBl, wm0, wn0, lane);
        __syncthreads();
    }

#pragma unroll
    for (int mi = 0; mi < 4; mi++)
#pragma unroll
        for (int h2 = 0; h2 < 2; h2++) {
            int m = row0 + wm0 + mi * 16 + (lane >> 2) + h2 * 8;
#pragma unroll
            for (int ni = 0; ni < 4; ni++) {
                int c = col0 + wn0 + ni * 8 + 2 * (lane & 3);
                float2 o;
                o.x = acc[mi][ni][h2 * 2 + 0] + __ldg(bo + c + 0);
                o.y = acc[mi][ni][h2 * 2 + 1] + __ldg(bo + c + 1);
                *(float2*)(out + (size_t)m * QD + c) = o;
            }
        }
}

// ---------------------------------------------------------------------------
// Launch
// ---------------------------------------------------------------------------
extern "C" void kernel_launch(void* const* d_in, const int* in_sizes, int n_in,
                              void* d_out, int out_size)
{
    const float* x     = (const float*)d_in[0];
    const int*   masks = (const int*)  d_in[1];
    const float* Wq    = (const float*)d_in[2];
    const float* Wk    = (const float*)d_in[3];
    const float* Wv    = (const float*)d_in[4];
    const float* Wo    = (const float*)d_in[5];
    const float* bo    = (const float*)d_in[6];
    float* out = (float*)d_out;
    (void)in_sizes; (void)n_in; (void)out_size;

    // Preprocessing
    conv_x_kernel<<<(ROWS * QD) / (256 * 8), 256>>>(x);
    w_trans_kernel<<<dim3(32, 32, 4), dim3(32, 8)>>>(Wq, Wk, Wv, Wo);
    mask_pack_kernel<<<(B_ * N_ * (N_ / 32)) / 256, 256>>>(masks);

    // Main pipeline
    qkv_hmma<<<dim3(INNER_ / 128, ROWS / 128, 3), 256>>>();
    scores_hmma<<<dim3(N_ / 128, N_ / 128, BH), 256>>>();
    pv_hmma<<<dim3(1, N_ / 128, BH), 256>>>();
    outproj_hmma<<<dim3(QD / 128, ROWS / 128), 256>>>(bo, out);
}

// round 9
// speedup vs baseline: 2.3315x; 1.2857x over previous
#include <cuda_runtime.h>
#include <cuda_bf16.h>
#include <cstdint>
#include <cstddef>

// ---------------------------------------------------------------------------
// Problem constants
// ---------------------------------------------------------------------------
#define B_     4
#define N_     2048
#define QD     1024
#define H_     16
#define DH     64
#define INNER_ 1024
#define BH     (B_ * H_)     // 64
#define ROWS   (B_ * N_)     // 8192

// ---------------------------------------------------------------------------
// Device scratch (allocation-free)
// ---------------------------------------------------------------------------
__device__ __nv_bfloat16 g_xh[(size_t)ROWS * QD];
__device__ __nv_bfloat16 g_xl[(size_t)ROWS * QD];
__device__ __nv_bfloat16 g_wth[(size_t)4 * QD * INNER_];   // [slot][n][k]
__device__ __nv_bfloat16 g_wtl[(size_t)4 * QD * INNER_];
__device__ __nv_bfloat16 g_qh[(size_t)BH * N_ * DH];
__device__ __nv_bfloat16 g_ql[(size_t)BH * N_ * DH];
__device__ __nv_bfloat16 g_kh[(size_t)BH * N_ * DH];
__device__ __nv_bfloat16 g_kl[(size_t)BH * N_ * DH];
__device__ __nv_bfloat16 g_vth[(size_t)BH * DH * N_];      // [bh][d][n]
__device__ __nv_bfloat16 g_vtl[(size_t)BH * DH * N_];
__device__ __nv_bfloat16 g_Eh[(size_t)BH * N_ * N_];       // exp(masked scores)
__device__ __nv_bfloat16 g_El[(size_t)BH * N_ * N_];
__device__ float         g_psum[(size_t)BH * N_ * 16];     // partial row sums
__device__ __nv_bfloat16 g_ath[(size_t)ROWS * INNER_];
__device__ __nv_bfloat16 g_atl[(size_t)ROWS * INNER_];
__device__ uint32_t      g_mb[(size_t)B_ * N_ * (N_ / 32)];

// ---------------------------------------------------------------------------
// Helpers
// ---------------------------------------------------------------------------
__device__ __forceinline__ uint32_t smem_to_u32(const void* p) {
    uint32_t a;
    asm("{ .reg .u64 t; cvta.to.shared.u64 t, %1; cvt.u32.u64 %0, t; }"
        : "=r"(a) : "l"(p));
    return a;
}

__device__ __forceinline__ void bsplit(float f, __nv_bfloat16& h, __nv_bfloat16& l) {
    h = __float2bfloat16(f);
    l = __float2bfloat16(f - __bfloat162float(h));
}

__device__ __forceinline__ void ldm_x4(uint32_t (&r)[4], uint32_t base, int row0,
                                       int ch0, int lane) {
    int m   = lane >> 3;
    int row = row0 + ((m & 1) << 3) + (lane & 7);
    int ch  = ch0 + (m >> 1);
    uint32_t addr = base + row * 80 + ch * 16;
    asm volatile("ldmatrix.sync.aligned.m8n8.x4.shared.b16 {%0,%1,%2,%3}, [%4];"
                 : "=r"(r[0]), "=r"(r[1]), "=r"(r[2]), "=r"(r[3]) : "r"(addr));
}

__device__ __forceinline__ void mma_bf16(float (&d)[4], const uint32_t (&a)[4],
                                         uint32_t b0, uint32_t b1) {
    asm volatile(
        "mma.sync.aligned.m16n8k16.row.col.f32.bf16.bf16.f32 "
        "{%0,%1,%2,%3}, {%4,%5,%6,%7}, {%8,%9}, {%0,%1,%2,%3};"
        : "+f"(d[0]), "+f"(d[1]), "+f"(d[2]), "+f"(d[3])
        : "r"(a[0]), "r"(a[1]), "r"(a[2]), "r"(a[3]), "r"(b0), "r"(b1));
}

// Load one BK=32 chunk (4 tiles: Ah/Al with RA rows, Bh/Bl with RB rows) into
// smem with 80B row pitch.  All global LDGs are issued first (high MLP), then
// all STSs — registers live only within this call, fully consumed before the
// caller's __syncthreads().  Semantically identical to four sequential
// LDG/STS tile loops (the R3 structure), only the issue order differs.
template <int RA, int RB>
__device__ __forceinline__ void load_chunk(
    char* sAh_, char* sAl_, char* sBh_, char* sBl_,
    const __nv_bfloat16* gAh, const __nv_bfloat16* gAl,
    const __nv_bfloat16* gBh, const __nv_bfloat16* gBl,
    size_t ldA, size_t ldB, int tid)
{
    constexpr int NA = RA / 64;
    constexpr int NB = RB / 64;
    uint4 vAh[NA], vAl[NA], vBh[NB], vBl[NB];
#pragma unroll
    for (int j = 0; j < NA; j++) {
        int i = tid + j * 256, r = i >> 2, c = i & 3;
        vAh[j] = *((const uint4*)(gAh + (size_t)r * ldA) + c);
        vAl[j] = *((const uint4*)(gAl + (size_t)r * ldA) + c);
    }
#pragma unroll
    for (int j = 0; j < NB; j++) {
        int i = tid + j * 256, r = i >> 2, c = i & 3;
        vBh[j] = *((const uint4*)(gBh + (size_t)r * ldB) + c);
        vBl[j] = *((const uint4*)(gBl + (size_t)r * ldB) + c);
    }
#pragma unroll
    for (int j = 0; j < NA; j++) {
        int i = tid + j * 256, r = i >> 2, c = i & 3;
        *(uint4*)(sAh_ + r * 80 + c * 16) = vAh[j];
        *(uint4*)(sAl_ + r * 80 + c * 16) = vAl[j];
    }
#pragma unroll
    for (int j = 0; j < NB; j++) {
        int i = tid + j * 256, r = i >> 2, c = i & 3;
        *(uint4*)(sBh_ + r * 80 + c * 16) = vBh[j];
        *(uint4*)(sBl_ + r * 80 + c * 16) = vBl[j];
    }
}

// One BK=32 chunk of the hi/lo-compensated bf16 MMA (3 products).
template <int MI, int NI>
__device__ __forceinline__ void mma_tiles(
    float (&acc)[MI][NI][4],
    uint32_t sAh, uint32_t sAl, uint32_t sBh, uint32_t sBl,
    int wm0, int wn0, int lane)
{
#pragma unroll
    for (int ks = 0; ks < 2; ks++) {
        uint32_t ah[MI][4], al[MI][4];
#pragma unroll
        for (int mi = 0; mi < MI; mi++) {
            ldm_x4(ah[mi], sAh, wm0 + mi * 16, ks * 2, lane);
            ldm_x4(al[mi], sAl, wm0 + mi * 16, ks * 2, lane);
        }
#pragma unroll
        for (int nj = 0; nj < NI / 2; nj++) {
            uint32_t bh[4], bl[4];
            ldm_x4(bh, sBh, wn0 + nj * 16, ks * 2, lane);
            ldm_x4(bl, sBl, wn0 + nj * 16, ks * 2, lane);
#pragma unroll
            for (int mi = 0; mi < MI; mi++) {
                mma_bf16(acc[mi][nj * 2],     ah[mi], bh[0], bh[2]);
                mma_bf16(acc[mi][nj * 2],     al[mi], bh[0], bh[2]);
                mma_bf16(acc[mi][nj * 2],     ah[mi], bl[0], bl[2]);
                mma_bf16(acc[mi][nj * 2 + 1], ah[mi], bh[1], bh[3]);
                mma_bf16(acc[mi][nj * 2 + 1], al[mi], bh[1], bh[3]);
                mma_bf16(acc[mi][nj * 2 + 1], ah[mi], bl[1], bl[3]);
            }
        }
    }
}

// ---------------------------------------------------------------------------
// Preprocessing kernels
// ---------------------------------------------------------------------------
__global__ __launch_bounds__(256) void conv_x_kernel(const float* __restrict__ x)
{
    size_t i = ((size_t)blockIdx.x * 256 + threadIdx.x) * 8;
    float4 a = *(const float4*)(x + i);
    float4 b = *(const float4*)(x + i + 4);
    float v[8] = {a.x, a.y, a.z, a.w, b.x, b.y, b.z, b.w};
    __align__(16) __nv_bfloat16 h[8], l[8];
#pragma unroll
    for (int j = 0; j < 8; j++) bsplit(v[j], h[j], l[j]);
    *(uint4*)(g_xh + i) = *(uint4*)h;
    *(uint4*)(g_xl + i) = *(uint4*)l;
}

__global__ __launch_bounds__(256) void w_trans_kernel(
    const float* __restrict__ Wq, const float* __restrict__ Wk,
    const float* __restrict__ Wv, const float* __restrict__ Wo)
{
    const float* W = (blockIdx.z == 0) ? Wq : (blockIdx.z == 1) ? Wk
                   : (blockIdx.z == 2) ? Wv : Wo;
    __shared__ float t[32][33];
    int tx = threadIdx.x, ty = threadIdx.y;      // (32, 8)
    int n0 = blockIdx.x * 32, k0 = blockIdx.y * 32;
#pragma unroll
    for (int i = 0; i < 32; i += 8)
        t[ty + i][tx] = W[(size_t)(k0 + ty + i) * INNER_ + n0 + tx];
    __syncthreads();
    __nv_bfloat16* wh = g_wth + (size_t)blockIdx.z * QD * INNER_;
    __nv_bfloat16* wl = g_wtl + (size_t)blockIdx.z * QD * INNER_;
#pragma unroll
    for (int i = 0; i < 32; i += 8) {
        int n = n0 + ty + i, k = k0 + tx;
        __nv_bfloat16 h, l;
        bsplit(t[tx][ty + i], h, l);
        wh[(size_t)n * QD + k] = h;
        wl[(size_t)n * QD + k] = l;
    }
}

__global__ __launch_bounds__(256) void mask_pack_kernel(const int* __restrict__ m)
{
    size_t w = (size_t)blockIdx.x * 256 + threadIdx.x;
    const int* src = m + w * 32;
    uint32_t bits = 0;
#pragma unroll
    for (int j = 0; j < 32; j++) bits |= (uint32_t)(src[j] > 0) << j;
    g_mb[w] = bits;
}

// ---------------------------------------------------------------------------
// Kernel A: QKV projection.  BM=BN=128, BK=32, 8 warps (2x4), warp 64x32.
// ---------------------------------------------------------------------------
__global__ __launch_bounds__(256, 2) void qkv_hmma()
{
    __shared__ __align__(16) char sAh[128 * 80], sAl[128 * 80];
    __shared__ __align__(16) char sBh[128 * 80], sBl[128 * 80];

    const int tid = threadIdx.x, lane = tid & 31, w = tid >> 5;
    const int wm0 = (w >> 2) * 64, wn0 = (w & 3) * 32;
    const int z = blockIdx.z;
    const int row0 = blockIdx.y * 128, col0 = blockIdx.x * 128;

    const __nv_bfloat16* wh = g_wth + (size_t)z * QD * INNER_;
    const __nv_bfloat16* wl = g_wtl + (size_t)z * QD * INNER_;

    const uint32_t uAh = smem_to_u32(sAh), uAl = smem_to_u32(sAl);
    const uint32_t uBh = smem_to_u32(sBh), uBl = smem_to_u32(sBl);

    float acc[4][4][4] = {};

    for (int k0 = 0; k0 < QD; k0 += 32) {
        load_chunk<128, 128>(sAh, sAl, sBh, sBl,
                             g_xh + (size_t)row0 * QD + k0,
                             g_xl + (size_t)row0 * QD + k0,
                             wh + (size_t)col0 * QD + k0,
                             wl + (size_t)col0 * QD + k0,
                             QD, QD, tid);
        __syncthreads();
        mma_tiles<4, 4>(acc, uAh, uAl, uBh, uBl, wm0, wn0, lane);
        __syncthreads();
    }

    if (z < 2) {
        __nv_bfloat16* dh_ = (z == 0) ? g_qh : g_kh;
        __nv_bfloat16* dl_ = (z == 0) ? g_ql : g_kl;
#pragma unroll
        for (int mi = 0; mi < 4; mi++)
#pragma unroll
            for (int h2 = 0; h2 < 2; h2++) {
                int m = row0 + wm0 + mi * 16 + (lane >> 2) + h2 * 8;
                int b = m >> 11, n = m & (N_ - 1);
#pragma unroll
                for (int ni = 0; ni < 4; ni++) {
                    int c = col0 + wn0 + ni * 8 + 2 * (lane & 3);
                    int hh = c >> 6, dd = c & 63;
                    __nv_bfloat16 h0, l0, h1, l1;
                    bsplit(acc[mi][ni][h2 * 2 + 0], h0, l0);
                    bsplit(acc[mi][ni][h2 * 2 + 1], h1, l1);
                    size_t off = ((size_t)(b * H_ + hh) * N_ + n) * DH + dd;
                    __nv_bfloat162 ph; ph.x = h0; ph.y = h1;
                    __nv_bfloat162 pl; pl.x = l0; pl.y = l1;
                    *(__nv_bfloat162*)(dh_ + off) = ph;
                    *(__nv_bfloat162*)(dl_ + off) = pl;
                }
            }
    } else {
        // V: write transposed [bh][d][n]
#pragma unroll
        for (int mi = 0; mi < 4; mi++)
#pragma unroll
            for (int h2 = 0; h2 < 2; h2++) {
                int m = row0 + wm0 + mi * 16 + (lane >> 2) + h2 * 8;
                int b = m >> 11, n = m & (N_ - 1);
#pragma unroll
                for (int ni = 0; ni < 4; ni++)
#pragma unroll
                    for (int c01 = 0; c01 < 2; c01++) {
                        int c = col0 + wn0 + ni * 8 + 2 * (lane & 3) + c01;
                        int hh = c >> 6, dd = c & 63;
                        __nv_bfloat16 h, l;
                        bsplit(acc[mi][ni][h2 * 2 + c01], h, l);
                        size_t off = ((size_t)(b * H_ + hh) * DH + dd) * N_ + n;
                        g_vth[off] = h;
                        g_vtl[off] = l;
                    }
            }
    }
}

// ---------------------------------------------------------------------------
// Kernel B: scores + mask + exp.  Per (b,h): S tile 128x128, K=64.
// Writes E = exp(scale*QK^T) masked, bf16 hi/lo, plus partial row sums.
// ---------------------------------------------------------------------------
__global__ __launch_bounds__(256, 2) void scores_hmma()
{
    __shared__ __align__(16) char sAh[128 * 80], sAl[128 * 80];
    __shared__ __align__(16) char sBh[128 * 80], sBl[128 * 80];
    __shared__ float psum_s[128];

    const int tid = threadIdx.x, lane = tid & 31, w = tid >> 5;
    const int wm0 = (w >> 2) * 64, wn0 = (w & 3) * 32;
    const int z = blockIdx.z, b = z >> 4;
    const int row0 = blockIdx.y * 128, col0 = blockIdx.x * 128;

    if (tid < 128) psum_s[tid] = 0.f;

    const uint32_t uAh = smem_to_u32(sAh), uAl = smem_to_u32(sAl);
    const uint32_t uBh = smem_to_u32(sBh), uBl = smem_to_u32(sBl);

    const size_t qb = (size_t)z * N_ * DH;
    float acc[4][4][4] = {};

    for (int k0 = 0; k0 < DH; k0 += 32) {
        load_chunk<128, 128>(sAh, sAl, sBh, sBl,
                             g_qh + qb + (size_t)row0 * DH + k0,
                             g_ql + qb + (size_t)row0 * DH + k0,
                             g_kh + qb + (size_t)col0 * DH + k0,
                             g_kl + qb + (size_t)col0 * DH + k0,
                             DH, DH, tid);
        __syncthreads();
        mma_tiles<4, 4>(acc, uAh, uAl, uBh, uBl, wm0, wn0, lane);
        __syncthreads();
    }

    const int mword = (col0 + wn0) >> 5;
#pragma unroll
    for (int mi = 0; mi < 4; mi++)
#pragma unroll
        for (int h2 = 0; h2 < 2; h2++) {
            int rloc = wm0 + mi * 16 + (lane >> 2) + h2 * 8;
            int i = row0 + rloc;
            uint32_t mw = g_mb[((size_t)b * N_ + i) * (N_ / 32) + mword];
            size_t ebase = ((size_t)z * N_ + i) * N_;
            float rs = 0.f;
#pragma unroll
            for (int ni = 0; ni < 4; ni++) {
                int bit = ni * 8 + 2 * (lane & 3);
                float e0 = 0.f, e1 = 0.f;
                if ((mw >> bit) & 1u)
                    e0 = __expf(acc[mi][ni][h2 * 2 + 0] * 0.125f);
                if ((mw >> (bit + 1)) & 1u)
                    e1 = __expf(acc[mi][ni][h2 * 2 + 1] * 0.125f);
                rs += e0 + e1;
                __nv_bfloat16 h0, l0, h1, l1;
                bsplit(e0, h0, l0);
                bsplit(e1, h1, l1);
                size_t off = ebase + col0 + wn0 + ni * 8 + 2 * (lane & 3);
                __nv_bfloat162 ph; ph.x = h0; ph.y = h1;
                __nv_bfloat162 pl; pl.x = l0; pl.y = l1;
                *(__nv_bfloat162*)(g_Eh + off) = ph;
                *(__nv_bfloat162*)(g_El + off) = pl;
            }
            rs += __shfl_xor_sync(0xFFFFFFFF, rs, 1);
            rs += __shfl_xor_sync(0xFFFFFFFF, rs, 2);
            if ((lane & 3) == 0) atomicAdd(&psum_s[rloc], rs);
        }
    __syncthreads();
    if (tid < 128)
        g_psum[((size_t)z * N_ + row0 + tid) * 16 + blockIdx.x] = psum_s[tid];
}

// ---------------------------------------------------------------------------
// Kernel C: PV.  O[128x64] = (E/rowsum)[128x2048] @ V.  BM=128, BN=64,
// 8 warps (4x2), warp 32x32.
// ---------------------------------------------------------------------------
__global__ __launch_bounds__(256, 2) void pv_hmma()
{
    __shared__ __align__(16) char sAh[128 * 80], sAl[128 * 80];
    __shared__ __align__(16) char sBh[64 * 80], sBl[64 * 80];
    __shared__ float inv_s[128];

    const int tid = threadIdx.x, lane = tid & 31, w = tid >> 5;
    const int wm0 = (w >> 1) * 32, wn0 = (w & 1) * 32;
    const int z = blockIdx.z, b = z >> 4, hh = z & 15;
    const int row0 = blockIdx.y * 128;

    if (tid < 128) {
        const float* ps = g_psum + ((size_t)z * N_ + row0 + tid) * 16;
        float s = 0.f;
#pragma unroll
        for (int t = 0; t < 16; t++) s += ps[t];
        inv_s[tid] = 1.f / s;
    }

    const uint32_t uAh = smem_to_u32(sAh), uAl = smem_to_u32(sAl);
    const uint32_t uBh = smem_to_u32(sBh), uBl = smem_to_u32(sBl);

    const size_t eb = (size_t)z * N_ * N_;
    const size_t vb = (size_t)z * DH * N_;
    float acc[2][4][4] = {};

    for (int k0 = 0; k0 < N_; k0 += 32) {
        load_chunk<128, 64>(sAh, sAl, sBh, sBl,
                            g_Eh + eb + (size_t)row0 * N_ + k0,
                            g_El + eb + (size_t)row0 * N_ + k0,
                            g_vth + vb + k0,
                            g_vtl + vb + k0,
                            N_, N_, tid);
        __syncthreads();
        mma_tiles<2, 4>(acc, uAh, uAl, uBh, uBl, wm0, wn0, lane);
        __syncthreads();
    }

#pragma unroll
    for (int mi = 0; mi < 2; mi++)
#pragma unroll
        for (int h2 = 0; h2 < 2; h2++) {
            int rloc = wm0 + mi * 16 + (lane >> 2) + h2 * 8;
            int i = row0 + rloc;
            float inv = inv_s[rloc];
#pragma unroll
            for (int ni = 0; ni < 4; ni++) {
                int c = wn0 + ni * 8 + 2 * (lane & 3);
                __nv_bfloat16 h0, l0, h1, l1;
                bsplit(acc[mi][ni][h2 * 2 + 0] * inv, h0, l0);
                bsplit(acc[mi][ni][h2 * 2 + 1] * inv, h1, l1);
                size_t off = ((size_t)(b * N_ + i)) * INNER_ + hh * 64 + c;
                __nv_bfloat162 ph; ph.x = h0; ph.y = h1;
                __nv_bfloat162 pl; pl.x = l0; pl.y = l1;
                *(__nv_bfloat162*)(g_ath + off) = ph;
                *(__nv_bfloat162*)(g_atl + off) = pl;
            }
        }
}

// ---------------------------------------------------------------------------
// Kernel D: output projection + bias -> d_out (fp32).
// ---------------------------------------------------------------------------
__global__ __launch_bounds__(256, 2) void outproj_hmma(
    const float* __restrict__ bo, float* __restrict__ out)
{
    __shared__ __align__(16) char sAh[128 * 80], sAl[128 * 80];
    __shared__ __align__(16) char sBh[128 * 80], sBl[128 * 80];

    const int tid = threadIdx.x, lane = tid & 31, w = tid >> 5;
    const int wm0 = (w >> 2) * 64, wn0 = (w & 3) * 32;
    const int row0 = blockIdx.y * 128, col0 = blockIdx.x * 128;

    const __nv_bfloat16* wh = g_wth + (size_t)3 * QD * INNER_;
    const __nv_bfloat16* wl = g_wtl + (size_t)3 * QD * INNER_;

    const uint32_t uAh = smem_to_u32(sAh), uAl = smem_to_u32(sAl);
    const uint32_t uBh = smem_to_u32(sBh), uBl = smem_to_u32(sBl);

    float acc[4][4][4] = {};

    for (int k0 = 0; k0 < INNER_; k0 += 32) {
        load_chunk<128, 128>(sAh, sAl, sBh, sBl,
                             g_ath + (size_t)row0 * INNER_ + k0,
                             g_atl + (size_t)row0 * INNER_ + k0,
                             wh + (size_t)col0 * QD + k0,
                             wl + (size_t)col0 * QD + k0,
                             INNER_, QD, tid);
        __syncthreads();
        mma_tiles<4, 4>(acc, uAh, uAl, uBh, uBl, wm0, wn0, lane);
        __syncthreads();
    }

#pragma unroll
    for (int mi = 0; mi < 4; mi++)
#pragma unroll
        for (int h2 = 0; h2 < 2; h2++) {
            int m = row0 + wm0 + mi * 16 + (lane >> 2) + h2 * 8;
#pragma unroll
            for (int ni = 0; ni < 4; ni++) {
                int c = col0 + wn0 + ni * 8 + 2 * (lane & 3);
                float2 o;
                o.x = acc[mi][ni][h2 * 2 + 0] + __ldg(bo + c + 0);
                o.y = acc[mi][ni][h2 * 2 + 1] + __ldg(bo + c + 1);
                *(float2*)(out + (size_t)m * QD + c) = o;
            }
        }
}

// ---------------------------------------------------------------------------
// Launch
// ---------------------------------------------------------------------------
extern "C" void kernel_launch(void* const* d_in, const int* in_sizes, int n_in,
                              void* d_out, int out_size)
{
    const float* x     = (const float*)d_in[0];
    const int*   masks = (const int*)  d_in[1];
    const float* Wq    = (const float*)d_in[2];
    const float* Wk    = (const float*)d_in[3];
    const float* Wv    = (const float*)d_in[4];
    const float* Wo    = (const float*)d_in[5];
    const float* bo    = (const float*)d_in[6];
    float* out = (float*)d_out;
    (void)in_sizes; (void)n_in; (void)out_size;

    // Preprocessing
    conv_x_kernel<<<(ROWS * QD) / (256 * 8), 256>>>(x);
    w_trans_kernel<<<dim3(32, 32, 4), dim3(32, 8)>>>(Wq, Wk, Wv, Wo);
    mask_pack_kernel<<<(B_ * N_ * (N_ / 32)) / 256, 256>>>(masks);

    // Main pipeline
    qkv_hmma<<<dim3(INNER_ / 128, ROWS / 128, 3), 256>>>();
    scores_hmma<<<dim3(N_ / 128, N_ / 128, BH), 256>>>();
    pv_hmma<<<dim3(1, N_ / 128, BH), 256>>>();
    outproj_hmma<<<dim3(QD / 128, ROWS / 128), 256>>>(bo, out);
}

// round 12
// speedup vs baseline: 2.6861x; 1.1521x over previous
#include <cuda_runtime.h>
#include <cuda_bf16.h>
#include <cstdint>
#include <cstddef>

// ---------------------------------------------------------------------------
// Problem constants
// ---------------------------------------------------------------------------
#define B_     4
#define N_     2048
#define QD     1024
#define H_     16
#define DH     64
#define INNER_ 1024
#define BH     (B_ * H_)     // 64
#define ROWS   (B_ * N_)     // 8192

// Smem tile geometry: BK=64 bf16 = 128B data per row, pitch 144B.
#define PITCH   144
#define TILE_A  (128 * PITCH)   // 18432
#define TILE_B64 (64 * PITCH)   // 9216
#define SM_BIG  (4 * TILE_A)                 // 73728
#define SM_PV   (2 * TILE_A + 2 * TILE_B64)  // 55296

// ---------------------------------------------------------------------------
// Device scratch (allocation-free)
// ---------------------------------------------------------------------------
__device__ __nv_bfloat16 g_xh[(size_t)ROWS * QD];
__device__ __nv_bfloat16 g_xl[(size_t)ROWS * QD];
__device__ __nv_bfloat16 g_wth[(size_t)4 * QD * INNER_];   // [slot][n][k]
__device__ __nv_bfloat16 g_wtl[(size_t)4 * QD * INNER_];
__device__ __nv_bfloat16 g_qh[(size_t)BH * N_ * DH];
__device__ __nv_bfloat16 g_ql[(size_t)BH * N_ * DH];
__device__ __nv_bfloat16 g_kh[(size_t)BH * N_ * DH];
__device__ __nv_bfloat16 g_kl[(size_t)BH * N_ * DH];
__device__ __nv_bfloat16 g_vth[(size_t)BH * DH * N_];      // [bh][d][n]
__device__ __nv_bfloat16 g_vtl[(size_t)BH * DH * N_];
__device__ __nv_bfloat16 g_Eh[(size_t)BH * N_ * N_];       // exp(masked scores)
__device__ __nv_bfloat16 g_El[(size_t)BH * N_ * N_];
__device__ float         g_psum[(size_t)BH * N_ * 16];     // partial row sums
__device__ __nv_bfloat16 g_ath[(size_t)ROWS * INNER_];
__device__ __nv_bfloat16 g_atl[(size_t)ROWS * INNER_];
__device__ uint32_t      g_mb[(size_t)B_ * N_ * (N_ / 32)];

// ---------------------------------------------------------------------------
// Helpers
// ---------------------------------------------------------------------------
__device__ __forceinline__ uint32_t smem_to_u32(const void* p) {
    uint32_t a;
    asm("{ .reg .u64 t; cvta.to.shared.u64 t, %1; cvt.u32.u64 %0, t; }"
        : "=r"(a) : "l"(p));
    return a;
}

__device__ __forceinline__ void bsplit(float f, __nv_bfloat16& h, __nv_bfloat16& l) {
    h = __float2bfloat16(f);
    l = __float2bfloat16(f - __bfloat162float(h));
}

__device__ __forceinline__ void ldm_x4(uint32_t (&r)[4], uint32_t base, int row0,
                                       int ch0, int lane) {
    int m   = lane >> 3;
    int row = row0 + ((m & 1) << 3) + (lane & 7);
    int ch  = ch0 + (m >> 1);
    uint32_t addr = base + row * PITCH + ch * 16;
    asm volatile("ldmatrix.sync.aligned.m8n8.x4.shared.b16 {%0,%1,%2,%3}, [%4];"
                 : "=r"(r[0]), "=r"(r[1]), "=r"(r[2]), "=r"(r[3]) : "r"(addr));
}

__device__ __forceinline__ void mma_bf16(float (&d)[4], const uint32_t (&a)[4],
                                         uint32_t b0, uint32_t b1) {
    asm volatile(
        "mma.sync.aligned.m16n8k16.row.col.f32.bf16.bf16.f32 "
        "{%0,%1,%2,%3}, {%4,%5,%6,%7}, {%8,%9}, {%0,%1,%2,%3};"
        : "+f"(d[0]), "+f"(d[1]), "+f"(d[2]), "+f"(d[3])
        : "r"(a[0]), "r"(a[1]), "r"(a[2]), "r"(a[3]), "r"(b0), "r"(b1));
}

// Load one BK=64 chunk (Ah/Al with RA rows, Bh/Bl with RB rows) into smem
// with PITCH-byte rows.  Two half-batches (hi tiles, then lo tiles); within
// each: all LDGs issued first, then all STSs.  Registers live only inside
// this call — nothing crosses the caller's __syncthreads().
template <int RA, int RB>
__device__ __forceinline__ void load_chunk64(
    char* sAh_, char* sAl_, char* sBh_, char* sBl_,
    const __nv_bfloat16* gAh, const __nv_bfloat16* gAl,
    const __nv_bfloat16* gBh, const __nv_bfloat16* gBl,
    size_t ldA, size_t ldB, int tid)
{
    constexpr int NA = RA / 32;   // uint4 per thread per tile (8 cols/row)
    constexpr int NB = RB / 32;
    {   // hi batch
        uint4 vA[NA], vB[NB];
#pragma unroll
        for (int j = 0; j < NA; j++) {
            int i = tid + j * 256, r = i >> 3, c = i & 7;
            vA[j] = *((const uint4*)(gAh + (size_t)r * ldA) + c);
        }
#pragma unroll
        for (int j = 0; j < NB; j++) {
            int i = tid + j * 256, r = i >> 3, c = i & 7;
            vB[j] = *((const uint4*)(gBh + (size_t)r * ldB) + c);
        }
#pragma unroll
        for (int j = 0; j < NA; j++) {
            int i = tid + j * 256, r = i >> 3, c = i & 7;
            *(uint4*)(sAh_ + r * PITCH + c * 16) = vA[j];
        }
#pragma unroll
        for (int j = 0; j < NB; j++) {
            int i = tid + j * 256, r = i >> 3, c = i & 7;
            *(uint4*)(sBh_ + r * PITCH + c * 16) = vB[j];
        }
    }
    {   // lo batch
        uint4 vA[NA], vB[NB];
#pragma unroll
        for (int j = 0; j < NA; j++) {
            int i = tid + j * 256, r = i >> 3, c = i & 7;
            vA[j] = *((const uint4*)(gAl + (size_t)r * ldA) + c);
        }
#pragma unroll
        for (int j = 0; j < NB; j++) {
            int i = tid + j * 256, r = i >> 3, c = i & 7;
            vB[j] = *((const uint4*)(gBl + (size_t)r * ldB) + c);
        }
#pragma unroll
        for (int j = 0; j < NA; j++) {
            int i = tid + j * 256, r = i >> 3, c = i & 7;
            *(uint4*)(sAl_ + r * PITCH + c * 16) = vA[j];
        }
#pragma unroll
        for (int j = 0; j < NB; j++) {
            int i = tid + j * 256, r = i >> 3, c = i & 7;
            *(uint4*)(sBl_ + r * PITCH + c * 16) = vB[j];
        }
    }
}

// One BK=64 chunk of the hi/lo-compensated bf16 MMA (3 products, 4 K-slices).
template <int MI, int NI>
__device__ __forceinline__ void mma_tiles(
    float (&acc)[MI][NI][4],
    uint32_t sAh, uint32_t sAl, uint32_t sBh, uint32_t sBl,
    int wm0, int wn0, int lane)
{
#pragma unroll
    for (int ks = 0; ks < 4; ks++) {
        uint32_t ah[MI][4], al[MI][4];
#pragma unroll
        for (int mi = 0; mi < MI; mi++) {
            ldm_x4(ah[mi], sAh, wm0 + mi * 16, ks * 2, lane);
            ldm_x4(al[mi], sAl, wm0 + mi * 16, ks * 2, lane);
        }
#pragma unroll
        for (int nj = 0; nj < NI / 2; nj++) {
            uint32_t bh[4], bl[4];
            ldm_x4(bh, sBh, wn0 + nj * 16, ks * 2, lane);
            ldm_x4(bl, sBl, wn0 + nj * 16, ks * 2, lane);
#pragma unroll
            for (int mi = 0; mi < MI; mi++) {
                mma_bf16(acc[mi][nj * 2],     ah[mi], bh[0], bh[2]);
                mma_bf16(acc[mi][nj * 2],     al[mi], bh[0], bh[2]);
                mma_bf16(acc[mi][nj * 2],     ah[mi], bl[0], bl[2]);
                mma_bf16(acc[mi][nj * 2 + 1], ah[mi], bh[1], bh[3]);
                mma_bf16(acc[mi][nj * 2 + 1], al[mi], bh[1], bh[3]);
                mma_bf16(acc[mi][nj * 2 + 1], ah[mi], bl[1], bl[3]);
            }
        }
    }
}

// ---------------------------------------------------------------------------
// Preprocessing kernels
// ---------------------------------------------------------------------------
__global__ __launch_bounds__(256) void conv_x_kernel(const float* __restrict__ x)
{
    size_t i = ((size_t)blockIdx.x * 256 + threadIdx.x) * 8;
    float4 a = *(const float4*)(x + i);
    float4 b = *(const float4*)(x + i + 4);
    float v[8] = {a.x, a.y, a.z, a.w, b.x, b.y, b.z, b.w};
    __align__(16) __nv_bfloat16 h[8], l[8];
#pragma unroll
    for (int j = 0; j < 8; j++) bsplit(v[j], h[j], l[j]);
    *(uint4*)(g_xh + i) = *(uint4*)h;
    *(uint4*)(g_xl + i) = *(uint4*)l;
}

__global__ __launch_bounds__(256) void w_trans_kernel(
    const float* __restrict__ Wq, const float* __restrict__ Wk,
    const float* __restrict__ Wv, const float* __restrict__ Wo)
{
    const float* W = (blockIdx.z == 0) ? Wq : (blockIdx.z == 1) ? Wk
                   : (blockIdx.z == 2) ? Wv : Wo;
    __shared__ float t[32][33];
    int tx = threadIdx.x, ty = threadIdx.y;      // (32, 8)
    int n0 = blockIdx.x * 32, k0 = blockIdx.y * 32;
#pragma unroll
    for (int i = 0; i < 32; i += 8)
        t[ty + i][tx] = W[(size_t)(k0 + ty + i) * INNER_ + n0 + tx];
    __syncthreads();
    __nv_bfloat16* wh = g_wth + (size_t)blockIdx.z * QD * INNER_;
    __nv_bfloat16* wl = g_wtl + (size_t)blockIdx.z * QD * INNER_;
#pragma unroll
    for (int i = 0; i < 32; i += 8) {
        int n = n0 + ty + i, k = k0 + tx;
        __nv_bfloat16 h, l;
        bsplit(t[tx][ty + i], h, l);
        wh[(size_t)n * QD + k] = h;
        wl[(size_t)n * QD + k] = l;
    }
}

__global__ __launch_bounds__(256) void mask_pack_kernel(const int* __restrict__ m)
{
    size_t w = (size_t)blockIdx.x * 256 + threadIdx.x;
    const int* src = m + w * 32;
    uint32_t bits = 0;
#pragma unroll
    for (int j = 0; j < 32; j++) bits |= (uint32_t)(src[j] > 0) << j;
    g_mb[w] = bits;
}

// ---------------------------------------------------------------------------
// Kernel A: QKV projection.  BM=BN=128, BK=64, 8 warps (2x4), warp 64x32.
// ---------------------------------------------------------------------------
__global__ __launch_bounds__(256, 2) void qkv_hmma()
{
    extern __shared__ __align__(16) char smem[];
    char* sAh = smem;
    char* sAl = smem + TILE_A;
    char* sBh = smem + 2 * TILE_A;
    char* sBl = smem + 3 * TILE_A;

    const int tid = threadIdx.x, lane = tid & 31, w = tid >> 5;
    const int wm0 = (w >> 2) * 64, wn0 = (w & 3) * 32;
    const int z = blockIdx.z;
    const int row0 = blockIdx.y * 128, col0 = blockIdx.x * 128;

    const __nv_bfloat16* wh = g_wth + (size_t)z * QD * INNER_;
    const __nv_bfloat16* wl = g_wtl + (size_t)z * QD * INNER_;

    const uint32_t uAh = smem_to_u32(sAh), uAl = smem_to_u32(sAl);
    const uint32_t uBh = smem_to_u32(sBh), uBl = smem_to_u32(sBl);

    float acc[4][4][4] = {};

    for (int k0 = 0; k0 < QD; k0 += 64) {
        load_chunk64<128, 128>(sAh, sAl, sBh, sBl,
                               g_xh + (size_t)row0 * QD + k0,
                               g_xl + (size_t)row0 * QD + k0,
                               wh + (size_t)col0 * QD + k0,
                               wl + (size_t)col0 * QD + k0,
                               QD, QD, tid);
        __syncthreads();
        mma_tiles<4, 4>(acc, uAh, uAl, uBh, uBl, wm0, wn0, lane);
        __syncthreads();
    }

    if (z < 2) {
        __nv_bfloat16* dh_ = (z == 0) ? g_qh : g_kh;
        __nv_bfloat16* dl_ = (z == 0) ? g_ql : g_kl;
#pragma unroll
        for (int mi = 0; mi < 4; mi++)
#pragma unroll
            for (int h2 = 0; h2 < 2; h2++) {
                int m = row0 + wm0 + mi * 16 + (lane >> 2) + h2 * 8;
                int b = m >> 11, n = m & (N_ - 1);
#pragma unroll
                for (int ni = 0; ni < 4; ni++) {
                    int c = col0 + wn0 + ni * 8 + 2 * (lane & 3);
                    int hh = c >> 6, dd = c & 63;
                    __nv_bfloat16 h0, l0, h1, l1;
                    bsplit(acc[mi][ni][h2 * 2 + 0], h0, l0);
                    bsplit(acc[mi][ni][h2 * 2 + 1], h1, l1);
                    size_t off = ((size_t)(b * H_ + hh) * N_ + n) * DH + dd;
                    __nv_bfloat162 ph; ph.x = h0; ph.y = h1;
                    __nv_bfloat162 pl; pl.x = l0; pl.y = l1;
                    *(__nv_bfloat162*)(dh_ + off) = ph;
                    *(__nv_bfloat162*)(dl_ + off) = pl;
                }
            }
    } else {
        // V: write transposed [bh][d][n]
#pragma unroll
        for (int mi = 0; mi < 4; mi++)
#pragma unroll
            for (int h2 = 0; h2 < 2; h2++) {
                int m = row0 + wm0 + mi * 16 + (lane >> 2) + h2 * 8;
                int b = m >> 11, n = m & (N_ - 1);
#pragma unroll
                for (int ni = 0; ni < 4; ni++)
#pragma unroll
                    for (int c01 = 0; c01 < 2; c01++) {
                        int c = col0 + wn0 + ni * 8 + 2 * (lane & 3) + c01;
                        int hh = c >> 6, dd = c & 63;
                        __nv_bfloat16 h, l;
                        bsplit(acc[mi][ni][h2 * 2 + c01], h, l);
                        size_t off = ((size_t)(b * H_ + hh) * DH + dd) * N_ + n;
                        g_vth[off] = h;
                        g_vtl[off] = l;
                    }
            }
    }
}

// ---------------------------------------------------------------------------
// Kernel B: scores + mask + exp.  Per (b,h): S tile 128x128, K=64 (1 chunk).
// ---------------------------------------------------------------------------
__global__ __launch_bounds__(256, 2) void scores_hmma()
{
    extern __shared__ __align__(16) char smem[];
    __shared__ float psum_s[128];
    char* sAh = smem;
    char* sAl = smem + TILE_A;
    char* sBh = smem + 2 * TILE_A;
    char* sBl = smem + 3 * TILE_A;

    const int tid = threadIdx.x, lane = tid & 31, w = tid >> 5;
    const int wm0 = (w >> 2) * 64, wn0 = (w & 3) * 32;
    const int z = blockIdx.z, b = z >> 4;
    const int row0 = blockIdx.y * 128, col0 = blockIdx.x * 128;

    if (tid < 128) psum_s[tid] = 0.f;

    const uint32_t uAh = smem_to_u32(sAh), uAl = smem_to_u32(sAl);
    const uint32_t uBh = smem_to_u32(sBh), uBl = smem_to_u32(sBl);

    const size_t qb = (size_t)z * N_ * DH;
    float acc[4][4][4] = {};

    load_chunk64<128, 128>(sAh, sAl, sBh, sBl,
                           g_qh + qb + (size_t)row0 * DH,
                           g_ql + qb + (size_t)row0 * DH,
                           g_kh + qb + (size_t)col0 * DH,
                           g_kl + qb + (size_t)col0 * DH,
                           DH, DH, tid);
    __syncthreads();
    mma_tiles<4, 4>(acc, uAh, uAl, uBh, uBl, wm0, wn0, lane);
    __syncthreads();

    const int mword = (col0 + wn0) >> 5;
#pragma unroll
    for (int mi = 0; mi < 4; mi++)
#pragma unroll
        for (int h2 = 0; h2 < 2; h2++) {
            int rloc = wm0 + mi * 16 + (lane >> 2) + h2 * 8;
            int i = row0 + rloc;
            uint32_t mw = g_mb[((size_t)b * N_ + i) * (N_ / 32) + mword];
            size_t ebase = ((size_t)z * N_ + i) * N_;
            float rs = 0.f;
#pragma unroll
            for (int ni = 0; ni < 4; ni++) {
                int bit = ni * 8 + 2 * (lane & 3);
                float e0 = 0.f, e1 = 0.f;
                if ((mw >> bit) & 1u)
                    e0 = __expf(acc[mi][ni][h2 * 2 + 0] * 0.125f);
                if ((mw >> (bit + 1)) & 1u)
                    e1 = __expf(acc[mi][ni][h2 * 2 + 1] * 0.125f);
                rs += e0 + e1;
                __nv_bfloat16 h0, l0, h1, l1;
                bsplit(e0, h0, l0);
                bsplit(e1, h1, l1);
                size_t off = ebase + col0 + wn0 + ni * 8 + 2 * (lane & 3);
                __nv_bfloat162 ph; ph.x = h0; ph.y = h1;
                __nv_bfloat162 pl; pl.x = l0; pl.y = l1;
                *(__nv_bfloat162*)(g_Eh + off) = ph;
                *(__nv_bfloat162*)(g_El + off) = pl;
            }
            rs += __shfl_xor_sync(0xFFFFFFFF, rs, 1);
            rs += __shfl_xor_sync(0xFFFFFFFF, rs, 2);
            if ((lane & 3) == 0) atomicAdd(&psum_s[rloc], rs);
        }
    __syncthreads();
    if (tid < 128)
        g_psum[((size_t)z * N_ + row0 + tid) * 16 + blockIdx.x] = psum_s[tid];
}

// ---------------------------------------------------------------------------
// Kernel C: PV.  O[128x64] = (E/rowsum)[128x2048] @ V.  32 chunks of 64.
// ---------------------------------------------------------------------------
__global__ __launch_bounds__(256, 2) void pv_hmma()
{
    extern __shared__ __align__(16) char smem[];
    __shared__ float inv_s[128];
    char* sAh = smem;
    char* sAl = smem + TILE_A;
    char* sBh = smem + 2 * TILE_A;
    char* sBl = smem + 2 * TILE_A + TILE_B64;

    const int tid = threadIdx.x, lane = tid & 31, w = tid >> 5;
    const int wm0 = (w >> 1) * 32, wn0 = (w & 1) * 32;
    const int z = blockIdx.z, b = z >> 4, hh = z & 15;
    const int row0 = blockIdx.y * 128;

    if (tid < 128) {
        const float* ps = g_psum + ((size_t)z * N_ + row0 + tid) * 16;
        float s = 0.f;
#pragma unroll
        for (int t = 0; t < 16; t++) s += ps[t];
        inv_s[tid] = 1.f / s;
    }

    const uint32_t uAh = smem_to_u32(sAh), uAl = smem_to_u32(sAl);
    const uint32_t uBh = smem_to_u32(sBh), uBl = smem_to_u32(sBl);

    const size_t eb = (size_t)z * N_ * N_;
    const size_t vb = (size_t)z * DH * N_;
    float acc[2][4][4] = {};

    for (int k0 = 0; k0 < N_; k0 += 64) {
        load_chunk64<128, 64>(sAh, sAl, sBh, sBl,
                              g_Eh + eb + (size_t)row0 * N_ + k0,
                              g_El + eb + (size_t)row0 * N_ + k0,
                              g_vth + vb + k0,
                              g_vtl + vb + k0,
                              N_, N_, tid);
        __syncthreads();
        mma_tiles<2, 4>(acc, uAh, uAl, uBh, uBl, wm0, wn0, lane);
        __syncthreads();
    }

#pragma unroll
    for (int mi = 0; mi < 2; mi++)
#pragma unroll
        for (int h2 = 0; h2 < 2; h2++) {
            int rloc = wm0 + mi * 16 + (lane >> 2) + h2 * 8;
            int i = row0 + rloc;
            float inv = inv_s[rloc];
#pragma unroll
            for (int ni = 0; ni < 4; ni++) {
                int c = wn0 + ni * 8 + 2 * (lane & 3);
                __nv_bfloat16 h0, l0, h1, l1;
                bsplit(acc[mi][ni][h2 * 2 + 0] * inv, h0, l0);
                bsplit(acc[mi][ni][h2 * 2 + 1] * inv, h1, l1);
                size_t off = ((size_t)(b * N_ + i)) * INNER_ + hh * 64 + c;
                __nv_bfloat162 ph; ph.x = h0; ph.y = h1;
                __nv_bfloat162 pl; pl.x = l0; pl.y = l1;
                *(__nv_bfloat162*)(g_ath + off) = ph;
                *(__nv_bfloat162*)(g_atl + off) = pl;
            }
        }
}

// ---------------------------------------------------------------------------
// Kernel D: output projection + bias -> d_out (fp32).  16 chunks of 64.
// ---------------------------------------------------------------------------
__global__ __launch_bounds__(256, 2) void outproj_hmma(
    const float* __restrict__ bo, float* __restrict__ out)
{
    extern __shared__ __align__(16) char smem[];
    char* sAh = smem;
    char* sAl = smem + TILE_A;
    char* sBh = smem + 2 * TILE_A;
    char* sBl = smem + 3 * TILE_A;

    const int tid = threadIdx.x, lane = tid & 31, w = tid >> 5;
    const int wm0 = (w >> 2) * 64, wn0 = (w & 3) * 32;
    const int row0 = blockIdx.y * 128, col0 = blockIdx.x * 128;

    const __nv_bfloat16* wh = g_wth + (size_t)3 * QD * INNER_;
    const __nv_bfloat16* wl = g_wtl + (size_t)3 * QD * INNER_;

    const uint32_t uAh = smem_to_u32(sAh), uAl = smem_to_u32(sAl);
    const uint32_t uBh = smem_to_u32(sBh), uBl = smem_to_u32(sBl);

    float acc[4][4][4] = {};

    for (int k0 = 0; k0 < INNER_; k0 += 64) {
        load_chunk64<128, 128>(sAh, sAl, sBh, sBl,
                               g_ath + (size_t)row0 * INNER_ + k0,
                               g_atl + (size_t)row0 * INNER_ + k0,
                               wh + (size_t)col0 * QD + k0,
                               wl + (size_t)col0 * QD + k0,
                               INNER_, QD, tid);
        __syncthreads();
        mma_tiles<4, 4>(acc, uAh, uAl, uBh, uBl, wm0, wn0, lane);
        __syncthreads();
    }

#pragma unroll
    for (int mi = 0; mi < 4; mi++)
#pragma unroll
        for (int h2 = 0; h2 < 2; h2++) {
            int m = row0 + wm0 + mi * 16 + (lane >> 2) + h2 * 8;
#pragma unroll
            for (int ni = 0; ni < 4; ni++) {
                int c = col0 + wn0 + ni * 8 + 2 * (lane & 3);
                float2 o;
                o.x = acc[mi][ni][h2 * 2 + 0] + __ldg(bo + c + 0);
                o.y = acc[mi][ni][h2 * 2 + 1] + __ldg(bo + c + 1);
                *(float2*)(out + (size_t)m * QD + c) = o;
            }
        }
}

// ---------------------------------------------------------------------------
// Launch
// ---------------------------------------------------------------------------
extern "C" void kernel_launch(void* const* d_in, const int* in_sizes, int n_in,
                              void* d_out, int out_size)
{
    const float* x     = (const float*)d_in[0];
    const int*   masks = (const int*)  d_in[1];
    const float* Wq    = (const float*)d_in[2];
    const float* Wk    = (const float*)d_in[3];
    const float* Wv    = (const float*)d_in[4];
    const float* Wo    = (const float*)d_in[5];
    const float* bo    = (const float*)d_in[6];
    float* out = (float*)d_out;
    (void)in_sizes; (void)n_in; (void)out_size;

    // Idempotent, called every launch (no static guards).
    cudaFuncSetAttribute(qkv_hmma,     cudaFuncAttributeMaxDynamicSharedMemorySize, SM_BIG);
    cudaFuncSetAttribute(scores_hmma,  cudaFuncAttributeMaxDynamicSharedMemorySize, SM_BIG);
    cudaFuncSetAttribute(pv_hmma,      cudaFuncAttributeMaxDynamicSharedMemorySize, SM_PV);
    cudaFuncSetAttribute(outproj_hmma, cudaFuncAttributeMaxDynamicSharedMemorySize, SM_BIG);

    // Preprocessing
    conv_x_kernel<<<(ROWS * QD) / (256 * 8), 256>>>(x);
    w_trans_kernel<<<dim3(32, 32, 4), dim3(32, 8)>>>(Wq, Wk, Wv, Wo);
    mask_pack_kernel<<<(B_ * N_ * (N_ / 32)) / 256, 256>>>(masks);

    // Main pipeline
    qkv_hmma<<<dim3(INNER_ / 128, ROWS / 128, 3), 256, SM_BIG>>>();
    scores_hmma<<<dim3(N_ / 128, N_ / 128, BH), 256, SM_BIG>>>();
    pv_hmma<<<dim3(1, N_ / 128, BH), 256, SM_PV>>>();
    outproj_hmma<<<dim3(QD / 128, ROWS / 128), 256, SM_BIG>>>(bo, out);
}

// round 13
// speedup vs baseline: 2.7862x; 1.0372x over previous
#include <cuda_runtime.h>
#include <cuda_bf16.h>
#include <cstdint>
#include <cstddef>

// ---------------------------------------------------------------------------
// Problem constants
// ---------------------------------------------------------------------------
#define B_     4
#define N_     2048
#define QD     1024
#define H_     16
#define DH     64
#define INNER_ 1024
#define BH     (B_ * H_)     // 64
#define ROWS   (B_ * N_)     // 8192

// Smem tile geometry
#define PITCH   144                     // 64-col bf16 tiles (128B data)
#define PITCH_P 272                     // 128-col bf16 tiles (256B data)
#define TILE_A  (128 * PITCH)           // 18432
#define TILE_B64 (64 * PITCH)           // 9216
#define TILE_V  (64 * PITCH_P)          // 17408
#define TILE_P  (128 * PITCH_P)         // 34816
#define SM_BIG  (4 * TILE_A)            // 73728 (qkv / outproj)

// Fused attention smem layout
#define OFF_QH  0
#define OFF_QL  (OFF_QH + TILE_A)
#define OFF_KH  (OFF_QL + TILE_A)
#define OFF_KL  (OFF_KH + TILE_A)
#define OFF_VH  (OFF_KL + TILE_A)
#define OFF_VL  (OFF_VH + TILE_V)
#define OFF_PH  (OFF_VL + TILE_V)
#define OFF_PL  (OFF_PH + TILE_P)
#define SM_FUSED (OFF_PL + TILE_P)      // 178176

// ---------------------------------------------------------------------------
// Device scratch (allocation-free)
// ---------------------------------------------------------------------------
__device__ __nv_bfloat16 g_xh[(size_t)ROWS * QD];
__device__ __nv_bfloat16 g_xl[(size_t)ROWS * QD];
__device__ __nv_bfloat16 g_wth[(size_t)4 * QD * INNER_];   // [slot][n][k]
__device__ __nv_bfloat16 g_wtl[(size_t)4 * QD * INNER_];
__device__ __nv_bfloat16 g_qh[(size_t)BH * N_ * DH];
__device__ __nv_bfloat16 g_ql[(size_t)BH * N_ * DH];
__device__ __nv_bfloat16 g_kh[(size_t)BH * N_ * DH];
__device__ __nv_bfloat16 g_kl[(size_t)BH * N_ * DH];
__device__ __nv_bfloat16 g_vth[(size_t)BH * DH * N_];      // [bh][d][n]
__device__ __nv_bfloat16 g_vtl[(size_t)BH * DH * N_];
__device__ __nv_bfloat16 g_ath[(size_t)ROWS * INNER_];
__device__ __nv_bfloat16 g_atl[(size_t)ROWS * INNER_];
__device__ uint32_t      g_mb[(size_t)B_ * N_ * (N_ / 32)];

// ---------------------------------------------------------------------------
// Helpers
// ---------------------------------------------------------------------------
__device__ __forceinline__ uint32_t smem_to_u32(const void* p) {
    uint32_t a;
    asm("{ .reg .u64 t; cvta.to.shared.u64 t, %1; cvt.u32.u64 %0, t; }"
        : "=r"(a) : "l"(p));
    return a;
}

__device__ __forceinline__ void bsplit(float f, __nv_bfloat16& h, __nv_bfloat16& l) {
    h = __float2bfloat16(f);
    l = __float2bfloat16(f - __bfloat162float(h));
}

template <int PIT>
__device__ __forceinline__ void ldm_x4(uint32_t (&r)[4], uint32_t base, int row0,
                                       int ch0, int lane) {
    int m   = lane >> 3;
    int row = row0 + ((m & 1) << 3) + (lane & 7);
    int ch  = ch0 + (m >> 1);
    uint32_t addr = base + row * PIT + ch * 16;
    asm volatile("ldmatrix.sync.aligned.m8n8.x4.shared.b16 {%0,%1,%2,%3}, [%4];"
                 : "=r"(r[0]), "=r"(r[1]), "=r"(r[2]), "=r"(r[3]) : "r"(addr));
}

__device__ __forceinline__ void mma_bf16(float (&d)[4], const uint32_t (&a)[4],
                                         uint32_t b0, uint32_t b1) {
    asm volatile(
        "mma.sync.aligned.m16n8k16.row.col.f32.bf16.bf16.f32 "
        "{%0,%1,%2,%3}, {%4,%5,%6,%7}, {%8,%9}, {%0,%1,%2,%3};"
        : "+f"(d[0]), "+f"(d[1]), "+f"(d[2]), "+f"(d[3])
        : "r"(a[0]), "r"(a[1]), "r"(a[2]), "r"(a[3]), "r"(b0), "r"(b1));
}

// Load one BK=64 chunk (Ah/Al RA rows, Bh/Bl RB rows) into smem (PITCH rows).
// Hi batch then lo batch; all LDGs of a batch issue before its STSs.
// Registers live only inside this call.
template <int RA, int RB>
__device__ __forceinline__ void load_chunk64(
    char* sAh_, char* sAl_, char* sBh_, char* sBl_,
    const __nv_bfloat16* gAh, const __nv_bfloat16* gAl,
    const __nv_bfloat16* gBh, const __nv_bfloat16* gBl,
    size_t ldA, size_t ldB, int tid)
{
    constexpr int NA = RA / 32;
    constexpr int NB = RB / 32;
    {
        uint4 vA[NA], vB[NB];
#pragma unroll
        for (int j = 0; j < NA; j++) {
            int i = tid + j * 256, r = i >> 3, c = i & 7;
            vA[j] = *((const uint4*)(gAh + (size_t)r * ldA) + c);
        }
#pragma unroll
        for (int j = 0; j < NB; j++) {
            int i = tid + j * 256, r = i >> 3, c = i & 7;
            vB[j] = *((const uint4*)(gBh + (size_t)r * ldB) + c);
        }
#pragma unroll
        for (int j = 0; j < NA; j++) {
            int i = tid + j * 256, r = i >> 3, c = i & 7;
            *(uint4*)(sAh_ + r * PITCH + c * 16) = vA[j];
        }
#pragma unroll
        for (int j = 0; j < NB; j++) {
            int i = tid + j * 256, r = i >> 3, c = i & 7;
            *(uint4*)(sBh_ + r * PITCH + c * 16) = vB[j];
        }
    }
    {
        uint4 vA[NA], vB[NB];
#pragma unroll
        for (int j = 0; j < NA; j++) {
            int i = tid + j * 256, r = i >> 3, c = i & 7;
            vA[j] = *((const uint4*)(gAl + (size_t)r * ldA) + c);
        }
#pragma unroll
        for (int j = 0; j < NB; j++) {
            int i = tid + j * 256, r = i >> 3, c = i & 7;
            vB[j] = *((const uint4*)(gBl + (size_t)r * ldB) + c);
        }
#pragma unroll
        for (int j = 0; j < NA; j++) {
            int i = tid + j * 256, r = i >> 3, c = i & 7;
            *(uint4*)(sAl_ + r * PITCH + c * 16) = vA[j];
        }
#pragma unroll
        for (int j = 0; j < NB; j++) {
            int i = tid + j * 256, r = i >> 3, c = i & 7;
            *(uint4*)(sBl_ + r * PITCH + c * 16) = vB[j];
        }
    }
}

// Fused-kernel loader: K block (128x64, PITCH) + V block (64x128, PITCH_P),
// hi and lo limbs.  All 16 LDGs issue before the 16 STSs.
__device__ __forceinline__ void load_kv(
    char* sKh_, char* sKl_, char* sVh_, char* sVl_,
    const __nv_bfloat16* gKh, const __nv_bfloat16* gKl,
    const __nv_bfloat16* gVh, const __nv_bfloat16* gVl,
    int tid)
{
    uint4 kh[4], kl[4], vh[4], vl[4];
#pragma unroll
    for (int j = 0; j < 4; j++) {
        int i = tid + j * 256, r = i >> 3, c = i & 7;
        kh[j] = *((const uint4*)(gKh + (size_t)r * DH) + c);
        kl[j] = *((const uint4*)(gKl + (size_t)r * DH) + c);
    }
#pragma unroll
    for (int j = 0; j < 4; j++) {
        int i = tid + j * 256, r = i >> 4, c = i & 15;
        vh[j] = *((const uint4*)(gVh + (size_t)r * N_) + c);
        vl[j] = *((const uint4*)(gVl + (size_t)r * N_) + c);
    }
#pragma unroll
    for (int j = 0; j < 4; j++) {
        int i = tid + j * 256, r = i >> 3, c = i & 7;
        *(uint4*)(sKh_ + r * PITCH + c * 16) = kh[j];
        *(uint4*)(sKl_ + r * PITCH + c * 16) = kl[j];
    }
#pragma unroll
    for (int j = 0; j < 4; j++) {
        int i = tid + j * 256, r = i >> 4, c = i & 15;
        *(uint4*)(sVh_ + r * PITCH_P + c * 16) = vh[j];
        *(uint4*)(sVl_ + r * PITCH_P + c * 16) = vl[j];
    }
}

// One chunk of the hi/lo-compensated bf16 MMA (3 products, KS K-slices).
template <int MI, int NI, int KS, int PA, int PB>
__device__ __forceinline__ void mma_tiles(
    float (&acc)[MI][NI][4],
    uint32_t sAh, uint32_t sAl, uint32_t sBh, uint32_t sBl,
    int wm0, int wn0, int lane)
{
#pragma unroll
    for (int ks = 0; ks < KS; ks++) {
        uint32_t ah[MI][4], al[MI][4];
#pragma unroll
        for (int mi = 0; mi < MI; mi++) {
            ldm_x4<PA>(ah[mi], sAh, wm0 + mi * 16, ks * 2, lane);
            ldm_x4<PA>(al[mi], sAl, wm0 + mi * 16, ks * 2, lane);
        }
#pragma unroll
        for (int nj = 0; nj < NI / 2; nj++) {
            uint32_t bh[4], bl[4];
            ldm_x4<PB>(bh, sBh, wn0 + nj * 16, ks * 2, lane);
            ldm_x4<PB>(bl, sBl, wn0 + nj * 16, ks * 2, lane);
#pragma unroll
            for (int mi = 0; mi < MI; mi++) {
                mma_bf16(acc[mi][nj * 2],     ah[mi], bh[0], bh[2]);
                mma_bf16(acc[mi][nj * 2],     al[mi], bh[0], bh[2]);
                mma_bf16(acc[mi][nj * 2],     ah[mi], bl[0], bl[2]);
                mma_bf16(acc[mi][nj * 2 + 1], ah[mi], bh[1], bh[3]);
                mma_bf16(acc[mi][nj * 2 + 1], al[mi], bh[1], bh[3]);
                mma_bf16(acc[mi][nj * 2 + 1], ah[mi], bl[1], bl[3]);
            }
        }
    }
}

// ---------------------------------------------------------------------------
// Preprocessing kernels
// ---------------------------------------------------------------------------
__global__ __launch_bounds__(256) void conv_x_kernel(const float* __restrict__ x)
{
    size_t i = ((size_t)blockIdx.x * 256 + threadIdx.x) * 8;
    float4 a = *(const float4*)(x + i);
    float4 b = *(const float4*)(x + i + 4);
    float v[8] = {a.x, a.y, a.z, a.w, b.x, b.y, b.z, b.w};
    __align__(16) __nv_bfloat16 h[8], l[8];
#pragma unroll
    for (int j = 0; j < 8; j++) bsplit(v[j], h[j], l[j]);
    *(uint4*)(g_xh + i) = *(uint4*)h;
    *(uint4*)(g_xl + i) = *(uint4*)l;
}

__global__ __launch_bounds__(256) void w_trans_kernel(
    const float* __restrict__ Wq, const float* __restrict__ Wk,
    const float* __restrict__ Wv, const float* __restrict__ Wo)
{
    const float* W = (blockIdx.z == 0) ? Wq : (blockIdx.z == 1) ? Wk
                   : (blockIdx.z == 2) ? Wv : Wo;
    __shared__ float t[32][33];
    int tx = threadIdx.x, ty = threadIdx.y;      // (32, 8)
    int n0 = blockIdx.x * 32, k0 = blockIdx.y * 32;
#pragma unroll
    for (int i = 0; i < 32; i += 8)
        t[ty + i][tx] = W[(size_t)(k0 + ty + i) * INNER_ + n0 + tx];
    __syncthreads();
    __nv_bfloat16* wh = g_wth + (size_t)blockIdx.z * QD * INNER_;
    __nv_bfloat16* wl = g_wtl + (size_t)blockIdx.z * QD * INNER_;
#pragma unroll
    for (int i = 0; i < 32; i += 8) {
        int n = n0 + ty + i, k = k0 + tx;
        __nv_bfloat16 h, l;
        bsplit(t[tx][ty + i], h, l);
        wh[(size_t)n * QD + k] = h;
        wl[(size_t)n * QD + k] = l;
    }
}

__global__ __launch_bounds__(256) void mask_pack_kernel(const int* __restrict__ m)
{
    size_t w = (size_t)blockIdx.x * 256 + threadIdx.x;
    const int* src = m + w * 32;
    uint32_t bits = 0;
#pragma unroll
    for (int j = 0; j < 32; j++) bits |= (uint32_t)(src[j] > 0) << j;
    g_mb[w] = bits;
}

// ---------------------------------------------------------------------------
// Kernel A: QKV projection.  BM=BN=128, BK=64, 8 warps (2x4), warp 64x32.
// ---------------------------------------------------------------------------
__global__ __launch_bounds__(256, 2) void qkv_hmma()
{
    extern __shared__ __align__(16) char smem[];
    char* sAh = smem;
    char* sAl = smem + TILE_A;
    char* sBh = smem + 2 * TILE_A;
    char* sBl = smem + 3 * TILE_A;

    const int tid = threadIdx.x, lane = tid & 31, w = tid >> 5;
    const int wm0 = (w >> 2) * 64, wn0 = (w & 3) * 32;
    const int z = blockIdx.z;
    const int row0 = blockIdx.y * 128, col0 = blockIdx.x * 128;

    const __nv_bfloat16* wh = g_wth + (size_t)z * QD * INNER_;
    const __nv_bfloat16* wl = g_wtl + (size_t)z * QD * INNER_;

    const uint32_t uAh = smem_to_u32(sAh), uAl = smem_to_u32(sAl);
    const uint32_t uBh = smem_to_u32(sBh), uBl = smem_to_u32(sBl);

    float acc[4][4][4] = {};

    for (int k0 = 0; k0 < QD; k0 += 64) {
        load_chunk64<128, 128>(sAh, sAl, sBh, sBl,
                               g_xh + (size_t)row0 * QD + k0,
                               g_xl + (size_t)row0 * QD + k0,
                               wh + (size_t)col0 * QD + k0,
                               wl + (size_t)col0 * QD + k0,
                               QD, QD, tid);
        __syncthreads();
        mma_tiles<4, 4, 4, PITCH, PITCH>(acc, uAh, uAl, uBh, uBl, wm0, wn0, lane);
        __syncthreads();
    }

    if (z < 2) {
        __nv_bfloat16* dh_ = (z == 0) ? g_qh : g_kh;
        __nv_bfloat16* dl_ = (z == 0) ? g_ql : g_kl;
#pragma unroll
        for (int mi = 0; mi < 4; mi++)
#pragma unroll
            for (int h2 = 0; h2 < 2; h2++) {
                int m = row0 + wm0 + mi * 16 + (lane >> 2) + h2 * 8;
                int b = m >> 11, n = m & (N_ - 1);
#pragma unroll
                for (int ni = 0; ni < 4; ni++) {
                    int c = col0 + wn0 + ni * 8 + 2 * (lane & 3);
                    int hh = c >> 6, dd = c & 63;
                    __nv_bfloat16 h0, l0, h1, l1;
                    bsplit(acc[mi][ni][h2 * 2 + 0], h0, l0);
                    bsplit(acc[mi][ni][h2 * 2 + 1], h1, l1);
                    size_t off = ((size_t)(b * H_ + hh) * N_ + n) * DH + dd;
                    __nv_bfloat162 ph; ph.x = h0; ph.y = h1;
                    __nv_bfloat162 pl; pl.x = l0; pl.y = l1;
                    *(__nv_bfloat162*)(dh_ + off) = ph;
                    *(__nv_bfloat162*)(dl_ + off) = pl;
                }
            }
    } else {
        // V: write transposed [bh][d][n]
#pragma unroll
        for (int mi = 0; mi < 4; mi++)
#pragma unroll
            for (int h2 = 0; h2 < 2; h2++) {
                int m = row0 + wm0 + mi * 16 + (lane >> 2) + h2 * 8;
                int b = m >> 11, n = m & (N_ - 1);
#pragma unroll
                for (int ni = 0; ni < 4; ni++)
#pragma unroll
                    for (int c01 = 0; c01 < 2; c01++) {
                        int c = col0 + wn0 + ni * 8 + 2 * (lane & 3) + c01;
                        int hh = c >> 6, dd = c & 63;
                        __nv_bfloat16 h, l;
                        bsplit(acc[mi][ni][h2 * 2 + c01], h, l);
                        size_t off = ((size_t)(b * H_ + hh) * DH + dd) * N_ + n;
                        g_vth[off] = h;
                        g_vtl[off] = l;
                    }
            }
    }
}

// ---------------------------------------------------------------------------
// Kernel B (fused): scores + mask + exp + PV, flash-style, P in smem.
// Grid: (N/128 row blocks, BH).  1 CTA/SM, 256 threads.
//   S warp layout 2x4 (warp 64x32); O warp layout 4x2 (warp 32x32).
// Row sums accumulate across key blocks (no max subtraction -> no rescale).
// ---------------------------------------------------------------------------
__global__ __launch_bounds__(256, 1) void attn_fused()
{
    extern __shared__ __align__(16) char smem[];
    __shared__ float psum_s[128];

    char* sQh = smem + OFF_QH;  char* sQl = smem + OFF_QL;
    char* sKh = smem + OFF_KH;  char* sKl = smem + OFF_KL;
    char* sVh = smem + OFF_VH;  char* sVl = smem + OFF_VL;
    char* sPh = smem + OFF_PH;  char* sPl = smem + OFF_PL;

    const int tid = threadIdx.x, lane = tid & 31, w = tid >> 5;
    const int wmS = (w >> 2) * 64, wnS = (w & 3) * 32;
    const int wmO = (w >> 1) * 32, wnO = (w & 1) * 32;
    const int z = blockIdx.y, b = z >> 4, hh = z & 15;
    const int row0 = blockIdx.x * 128;

    const size_t qb = (size_t)z * N_ * DH;
    const size_t vb = (size_t)z * DH * N_;

    const uint32_t uQh = smem_to_u32(sQh), uQl = smem_to_u32(sQl);
    const uint32_t uKh = smem_to_u32(sKh), uKl = smem_to_u32(sKl);
    const uint32_t uVh = smem_to_u32(sVh), uVl = smem_to_u32(sVl);
    const uint32_t uPh = smem_to_u32(sPh), uPl = smem_to_u32(sPl);

    // Load Q block (128x64 hi/lo) once; batched LDG->STS.
    {
        uint4 qh[4], ql[4];
#pragma unroll
        for (int j = 0; j < 4; j++) {
            int i = tid + j * 256, r = i >> 3, c = i & 7;
            qh[j] = *((const uint4*)(g_qh + qb + (size_t)(row0 + r) * DH) + c);
            ql[j] = *((const uint4*)(g_ql + qb + (size_t)(row0 + r) * DH) + c);
        }
#pragma unroll
        for (int j = 0; j < 4; j++) {
            int i = tid + j * 256, r = i >> 3, c = i & 7;
            *(uint4*)(sQh + r * PITCH + c * 16) = qh[j];
            *(uint4*)(sQl + r * PITCH + c * 16) = ql[j];
        }
    }
    if (tid < 128) psum_s[tid] = 0.f;

    float accO[2][4][4] = {};

    for (int j = 0; j < N_ / 128; j++) {
        __syncthreads();   // prior O-mma done with K/V/P; Q+psum visible (j=0)
        load_kv(sKh, sKl, sVh, sVl,
                g_kh + qb + (size_t)(j * 128) * DH,
                g_kl + qb + (size_t)(j * 128) * DH,
                g_vth + vb + j * 128,
                g_vtl + vb + j * 128,
                tid);
        __syncthreads();   // K/V visible

        float accS[4][4][4] = {};
        mma_tiles<4, 4, 4, PITCH, PITCH>(accS, uQh, uQl, uKh, uKl, wmS, wnS, lane);

        // mask + exp -> P (smem, bf16 hi/lo) + row-sum accumulation
        const int mword = (j * 128 + wnS) >> 5;
#pragma unroll
        for (int mi = 0; mi < 4; mi++)
#pragma unroll
            for (int h2 = 0; h2 < 2; h2++) {
                int rloc = wmS + mi * 16 + (lane >> 2) + h2 * 8;
                int i = row0 + rloc;
                uint32_t mw = g_mb[((size_t)b * N_ + i) * (N_ / 32) + mword];
                float rs = 0.f;
#pragma unroll
                for (int ni = 0; ni < 4; ni++) {
                    int bit = ni * 8 + 2 * (lane & 3);
                    float e0 = 0.f, e1 = 0.f;
                    if ((mw >> bit) & 1u)
                        e0 = __expf(accS[mi][ni][h2 * 2 + 0] * 0.125f);
                    if ((mw >> (bit + 1)) & 1u)
                        e1 = __expf(accS[mi][ni][h2 * 2 + 1] * 0.125f);
                    rs += e0 + e1;
                    __nv_bfloat16 h0, l0, h1, l1;
                    bsplit(e0, h0, l0);
                    bsplit(e1, h1, l1);
                    int col = wnS + ni * 8 + 2 * (lane & 3);
                    __nv_bfloat162 ph; ph.x = h0; ph.y = h1;
                    __nv_bfloat162 pl; pl.x = l0; pl.y = l1;
                    *(__nv_bfloat162*)(sPh + rloc * PITCH_P + col * 2) = ph;
                    *(__nv_bfloat162*)(sPl + rloc * PITCH_P + col * 2) = pl;
                }
                rs += __shfl_xor_sync(0xFFFFFFFF, rs, 1);
                rs += __shfl_xor_sync(0xFFFFFFFF, rs, 2);
                if ((lane & 3) == 0) atomicAdd(&psum_s[rloc], rs);
            }
        __syncthreads();   // P visible

        // O += P @ V   (A = P 128x128 k, B = V^T 64x128 k)
        mma_tiles<2, 4, 8, PITCH_P, PITCH_P>(accO, uPh, uPl, uVh, uVl, wmO, wnO, lane);
    }
    __syncthreads();

    // Normalize by row sum and write [b*N+i][h*64+c] hi/lo
#pragma unroll
    for (int mi = 0; mi < 2; mi++)
#pragma unroll
        for (int h2 = 0; h2 < 2; h2++) {
            int rloc = wmO + mi * 16 + (lane >> 2) + h2 * 8;
            int i = row0 + rloc;
            float inv = 1.f / psum_s[rloc];
#pragma unroll
            for (int ni = 0; ni < 4; ni++) {
                int c = wnO + ni * 8 + 2 * (lane & 3);
                __nv_bfloat16 h0, l0, h1, l1;
                bsplit(accO[mi][ni][h2 * 2 + 0] * inv, h0, l0);
                bsplit(accO[mi][ni][h2 * 2 + 1] * inv, h1, l1);
                size_t off = ((size_t)(b * N_ + i)) * INNER_ + hh * 64 + c;
                __nv_bfloat162 ph; ph.x = h0; ph.y = h1;
                __nv_bfloat162 pl; pl.x = l0; pl.y = l1;
                *(__nv_bfloat162*)(g_ath + off) = ph;
                *(__nv_bfloat162*)(g_atl + off) = pl;
            }
        }
}

// ---------------------------------------------------------------------------
// Kernel C: output projection + bias -> d_out (fp32).  16 chunks of 64.
// ---------------------------------------------------------------------------
__global__ __launch_bounds__(256, 2) void outproj_hmma(
    const float* __restrict__ bo, float* __restrict__ out)
{
    extern __shared__ __align__(16) char smem[];
    char* sAh = smem;
    char* sAl = smem + TILE_A;
    char* sBh = smem + 2 * TILE_A;
    char* sBl = smem + 3 * TILE_A;

    const int tid = threadIdx.x, lane = tid & 31, w = tid >> 5;
    const int wm0 = (w >> 2) * 64, wn0 = (w & 3) * 32;
    const int row0 = blockIdx.y * 128, col0 = blockIdx.x * 128;

    const __nv_bfloat16* wh = g_wth + (size_t)3 * QD * INNER_;
    const __nv_bfloat16* wl = g_wtl + (size_t)3 * QD * INNER_;

    const uint32_t uAh = smem_to_u32(sAh), uAl = smem_to_u32(sAl);
    const uint32_t uBh = smem_to_u32(sBh), uBl = smem_to_u32(sBl);

    float acc[4][4][4] = {};

    for (int k0 = 0; k0 < INNER_; k0 += 64) {
        load_chunk64<128, 128>(sAh, sAl, sBh, sBl,
                               g_ath + (size_t)row0 * INNER_ + k0,
                               g_atl + (size_t)row0 * INNER_ + k0,
                               wh + (size_t)col0 * QD + k0,
                               wl + (size_t)col0 * QD + k0,
                               INNER_, QD, tid);
        __syncthreads();
        mma_tiles<4, 4, 4, PITCH, PITCH>(acc, uAh, uAl, uBh, uBl, wm0, wn0, lane);
        __syncthreads();
    }

#pragma unroll
    for (int mi = 0; mi < 4; mi++)
#pragma unroll
        for (int h2 = 0; h2 < 2; h2++) {
            int m = row0 + wm0 + mi * 16 + (lane >> 2) + h2 * 8;
#pragma unroll
            for (int ni = 0; ni < 4; ni++) {
                int c = col0 + wn0 + ni * 8 + 2 * (lane & 3);
                float2 o;
                o.x = acc[mi][ni][h2 * 2 + 0] + __ldg(bo + c + 0);
                o.y = acc[mi][ni][h2 * 2 + 1] + __ldg(bo + c + 1);
                *(float2*)(out + (size_t)m * QD + c) = o;
            }
        }
}

// ---------------------------------------------------------------------------
// Launch
// ---------------------------------------------------------------------------
extern "C" void kernel_launch(void* const* d_in, const int* in_sizes, int n_in,
                              void* d_out, int out_size)
{
    const float* x     = (const float*)d_in[0];
    const int*   masks = (const int*)  d_in[1];
    const float* Wq    = (const float*)d_in[2];
    const float* Wk    = (const float*)d_in[3];
    const float* Wv    = (const float*)d_in[4];
    const float* Wo    = (const float*)d_in[5];
    const float* bo    = (const float*)d_in[6];
    float* out = (float*)d_out;
    (void)in_sizes; (void)n_in; (void)out_size;

    // Idempotent, called every launch (no static guards).
    cudaFuncSetAttribute(qkv_hmma,     cudaFuncAttributeMaxDynamicSharedMemorySize, SM_BIG);
    cudaFuncSetAttribute(attn_fused,   cudaFuncAttributeMaxDynamicSharedMemorySize, SM_FUSED);
    cudaFuncSetAttribute(outproj_hmma, cudaFuncAttributeMaxDynamicSharedMemorySize, SM_BIG);

    // Preprocessing
    conv_x_kernel<<<(ROWS * QD) / (256 * 8), 256>>>(x);
    w_trans_kernel<<<dim3(32, 32, 4), dim3(32, 8)>>>(Wq, Wk, Wv, Wo);
    mask_pack_kernel<<<(B_ * N_ * (N_ / 32)) / 256, 256>>>(masks);

    // Main pipeline
    qkv_hmma<<<dim3(INNER_ / 128, ROWS / 128, 3), 256, SM_BIG>>>();
    attn_fused<<<dim3(N_ / 128, BH), 256, SM_FUSED>>>();
    outproj_hmma<<<dim3(QD / 128, ROWS / 128), 256, SM_BIG>>>(bo, out);
}

// round 14
// speedup vs baseline: 3.7108x; 1.3319x over previous
#include <cuda_runtime.h>
#include <cuda_bf16.h>
#include <cuda_fp16.h>
#include <cstdint>
#include <cstddef>

// ---------------------------------------------------------------------------
// Problem constants
// ---------------------------------------------------------------------------
#define B_     4
#define N_     2048
#define QD     1024
#define H_     16
#define DH     64
#define INNER_ 1024
#define BH     (B_ * H_)     // 64
#define ROWS   (B_ * N_)     // 8192

// Smem tile geometry
#define PITCH   144                     // 64-col 16-bit tiles (128B data)
#define TILE_A  (128 * PITCH)           // 18432
#define TILE_K64 (64 * PITCH)           // 9216
#define SM_BIG  (4 * TILE_A)            // 73728 (qkv / outproj)

// Fused attention smem layout (key-block = 64)
#define OFF_QH  0
#define OFF_QL  (OFF_QH + TILE_A)       // Q: 128x64 hi/lo
#define OFF_KH  (OFF_QL + TILE_A)       // K: 64x64 hi/lo
#define OFF_KL  (OFF_KH + TILE_K64)
#define OFF_V   (OFF_KL + TILE_K64)     // V: 64(d)x64(keys) fp16
#define OFF_P   (OFF_V + TILE_K64)      // P: 128x64 fp16
#define SM_FUSED (OFF_P + TILE_A)       // 82944 -> 2 CTAs/SM

// ---------------------------------------------------------------------------
// Device scratch (allocation-free)
// ---------------------------------------------------------------------------
__device__ __nv_bfloat16 g_xh[(size_t)ROWS * QD];
__device__ __nv_bfloat16 g_xl[(size_t)ROWS * QD];
__device__ __nv_bfloat16 g_wth[(size_t)4 * QD * INNER_];   // [slot][n][k]
__device__ __nv_bfloat16 g_wtl[(size_t)4 * QD * INNER_];
__device__ __nv_bfloat16 g_qh[(size_t)BH * N_ * DH];
__device__ __nv_bfloat16 g_ql[(size_t)BH * N_ * DH];
__device__ __nv_bfloat16 g_kh[(size_t)BH * N_ * DH];
__device__ __nv_bfloat16 g_kl[(size_t)BH * N_ * DH];
__device__ __half        g_vt[(size_t)BH * DH * N_];       // [bh][d][n] fp16
__device__ __nv_bfloat16 g_ath[(size_t)ROWS * INNER_];
__device__ __nv_bfloat16 g_atl[(size_t)ROWS * INNER_];
__device__ uint32_t      g_mb[(size_t)B_ * N_ * (N_ / 32)];

// ---------------------------------------------------------------------------
// Helpers
// ---------------------------------------------------------------------------
__device__ __forceinline__ uint32_t smem_to_u32(const void* p) {
    uint32_t a;
    asm("{ .reg .u64 t; cvta.to.shared.u64 t, %1; cvt.u32.u64 %0, t; }"
        : "=r"(a) : "l"(p));
    return a;
}

__device__ __forceinline__ void bsplit(float f, __nv_bfloat16& h, __nv_bfloat16& l) {
    h = __float2bfloat16(f);
    l = __float2bfloat16(f - __bfloat162float(h));
}

template <int PIT>
__device__ __forceinline__ void ldm_x4(uint32_t (&r)[4], uint32_t base, int row0,
                                       int ch0, int lane) {
    int m   = lane >> 3;
    int row = row0 + ((m & 1) << 3) + (lane & 7);
    int ch  = ch0 + (m >> 1);
    uint32_t addr = base + row * PIT + ch * 16;
    asm volatile("ldmatrix.sync.aligned.m8n8.x4.shared.b16 {%0,%1,%2,%3}, [%4];"
                 : "=r"(r[0]), "=r"(r[1]), "=r"(r[2]), "=r"(r[3]) : "r"(addr));
}

__device__ __forceinline__ void mma_bf16(float (&d)[4], const uint32_t (&a)[4],
                                         uint32_t b0, uint32_t b1) {
    asm volatile(
        "mma.sync.aligned.m16n8k16.row.col.f32.bf16.bf16.f32 "
        "{%0,%1,%2,%3}, {%4,%5,%6,%7}, {%8,%9}, {%0,%1,%2,%3};"
        : "+f"(d[0]), "+f"(d[1]), "+f"(d[2]), "+f"(d[3])
        : "r"(a[0]), "r"(a[1]), "r"(a[2]), "r"(a[3]), "r"(b0), "r"(b1));
}

__device__ __forceinline__ void mma_f16(float (&d)[4], const uint32_t (&a)[4],
                                        uint32_t b0, uint32_t b1) {
    asm volatile(
        "mma.sync.aligned.m16n8k16.row.col.f32.f16.f16.f32 "
        "{%0,%1,%2,%3}, {%4,%5,%6,%7}, {%8,%9}, {%0,%1,%2,%3};"
        : "+f"(d[0]), "+f"(d[1]), "+f"(d[2]), "+f"(d[3])
        : "r"(a[0]), "r"(a[1]), "r"(a[2]), "r"(a[3]), "r"(b0), "r"(b1));
}

// Load one BK=64 chunk (Ah/Al RA rows, Bh/Bl RB rows) into smem (PITCH rows).
// Hi batch then lo batch; all LDGs of a batch issue before its STSs.
template <int RA, int RB>
__device__ __forceinline__ void load_chunk64(
    char* sAh_, char* sAl_, char* sBh_, char* sBl_,
    const __nv_bfloat16* gAh, const __nv_bfloat16* gAl,
    const __nv_bfloat16* gBh, const __nv_bfloat16* gBl,
    size_t ldA, size_t ldB, int tid)
{
    constexpr int NA = RA / 32;
    constexpr int NB = RB / 32;
    {
        uint4 vA[NA], vB[NB];
#pragma unroll
        for (int j = 0; j < NA; j++) {
            int i = tid + j * 256, r = i >> 3, c = i & 7;
            vA[j] = *((const uint4*)(gAh + (size_t)r * ldA) + c);
        }
#pragma unroll
        for (int j = 0; j < NB; j++) {
            int i = tid + j * 256, r = i >> 3, c = i & 7;
            vB[j] = *((const uint4*)(gBh + (size_t)r * ldB) + c);
        }
#pragma unroll
        for (int j = 0; j < NA; j++) {
            int i = tid + j * 256, r = i >> 3, c = i & 7;
            *(uint4*)(sAh_ + r * PITCH + c * 16) = vA[j];
        }
#pragma unroll
        for (int j = 0; j < NB; j++) {
            int i = tid + j * 256, r = i >> 3, c = i & 7;
            *(uint4*)(sBh_ + r * PITCH + c * 16) = vB[j];
        }
    }
    {
        uint4 vA[NA], vB[NB];
#pragma unroll
        for (int j = 0; j < NA; j++) {
            int i = tid + j * 256, r = i >> 3, c = i & 7;
            vA[j] = *((const uint4*)(gAl + (size_t)r * ldA) + c);
        }
#pragma unroll
        for (int j = 0; j < NB; j++) {
            int i = tid + j * 256, r = i >> 3, c = i & 7;
            vB[j] = *((const uint4*)(gBl + (size_t)r * ldB) + c);
        }
#pragma unroll
        for (int j = 0; j < NA; j++) {
            int i = tid + j * 256, r = i >> 3, c = i & 7;
            *(uint4*)(sAl_ + r * PITCH + c * 16) = vA[j];
        }
#pragma unroll
        for (int j = 0; j < NB; j++) {
            int i = tid + j * 256, r = i >> 3, c = i & 7;
            *(uint4*)(sBl_ + r * PITCH + c * 16) = vB[j];
        }
    }
}

// Fused-kernel loader: K block (64x64 hi/lo bf16) + V block (64x64 fp16).
// All LDGs issue before all STSs; registers live only inside this call.
__device__ __forceinline__ void load_kv64(
    char* sKh_, char* sKl_, char* sV_,
    const __nv_bfloat16* gKh, const __nv_bfloat16* gKl,
    const __half* gV, int tid)
{
    uint4 kh[2], kl[2], vv[2];
#pragma unroll
    for (int j = 0; j < 2; j++) {
        int i = tid + j * 256, r = i >> 3, c = i & 7;
        kh[j] = *((const uint4*)(gKh + (size_t)r * DH) + c);
        kl[j] = *((const uint4*)(gKl + (size_t)r * DH) + c);
        vv[j] = *((const uint4*)(gV + (size_t)r * N_) + c);
    }
#pragma unroll
    for (int j = 0; j < 2; j++) {
        int i = tid + j * 256, r = i >> 3, c = i & 7;
        *(uint4*)(sKh_ + r * PITCH + c * 16) = kh[j];
        *(uint4*)(sKl_ + r * PITCH + c * 16) = kl[j];
        *(uint4*)(sV_  + r * PITCH + c * 16) = vv[j];
    }
}

// One chunk of the hi/lo-compensated bf16 MMA (3 products, KS K-slices).
template <int MI, int NI, int KS, int PA, int PB>
__device__ __forceinline__ void mma_tiles(
    float (&acc)[MI][NI][4],
    uint32_t sAh, uint32_t sAl, uint32_t sBh, uint32_t sBl,
    int wm0, int wn0, int lane)
{
#pragma unroll
    for (int ks = 0; ks < KS; ks++) {
        uint32_t ah[MI][4], al[MI][4];
#pragma unroll
        for (int mi = 0; mi < MI; mi++) {
            ldm_x4<PA>(ah[mi], sAh, wm0 + mi * 16, ks * 2, lane);
            ldm_x4<PA>(al[mi], sAl, wm0 + mi * 16, ks * 2, lane);
        }
#pragma unroll
        for (int nj = 0; nj < NI / 2; nj++) {
            uint32_t bh[4], bl[4];
            ldm_x4<PB>(bh, sBh, wn0 + nj * 16, ks * 2, lane);
            ldm_x4<PB>(bl, sBl, wn0 + nj * 16, ks * 2, lane);
#pragma unroll
            for (int mi = 0; mi < MI; mi++) {
                mma_bf16(acc[mi][nj * 2],     ah[mi], bh[0], bh[2]);
                mma_bf16(acc[mi][nj * 2],     al[mi], bh[0], bh[2]);
                mma_bf16(acc[mi][nj * 2],     ah[mi], bl[0], bl[2]);
                mma_bf16(acc[mi][nj * 2 + 1], ah[mi], bh[1], bh[3]);
                mma_bf16(acc[mi][nj * 2 + 1], al[mi], bh[1], bh[3]);
                mma_bf16(acc[mi][nj * 2 + 1], ah[mi], bl[1], bl[3]);
            }
        }
    }
}

// ---------------------------------------------------------------------------
// Preprocessing kernels
// ---------------------------------------------------------------------------
__global__ __launch_bounds__(256) void conv_x_kernel(const float* __restrict__ x)
{
    size_t i = ((size_t)blockIdx.x * 256 + threadIdx.x) * 8;
    float4 a = *(const float4*)(x + i);
    float4 b = *(const float4*)(x + i + 4);
    float v[8] = {a.x, a.y, a.z, a.w, b.x, b.y, b.z, b.w};
    __align__(16) __nv_bfloat16 h[8], l[8];
#pragma unroll
    for (int j = 0; j < 8; j++) bsplit(v[j], h[j], l[j]);
    *(uint4*)(g_xh + i) = *(uint4*)h;
    *(uint4*)(g_xl + i) = *(uint4*)l;
}

__global__ __launch_bounds__(256) void w_trans_kernel(
    const float* __restrict__ Wq, const float* __restrict__ Wk,
    const float* __restrict__ Wv, const float* __restrict__ Wo)
{
    const float* W = (blockIdx.z == 0) ? Wq : (blockIdx.z == 1) ? Wk
                   : (blockIdx.z == 2) ? Wv : Wo;
    __shared__ float t[32][33];
    int tx = threadIdx.x, ty = threadIdx.y;      // (32, 8)
    int n0 = blockIdx.x * 32, k0 = blockIdx.y * 32;
#pragma unroll
    for (int i = 0; i < 32; i += 8)
        t[ty + i][tx] = W[(size_t)(k0 + ty + i) * INNER_ + n0 + tx];
    __syncthreads();
    __nv_bfloat16* wh = g_wth + (size_t)blockIdx.z * QD * INNER_;
    __nv_bfloat16* wl = g_wtl + (size_t)blockIdx.z * QD * INNER_;
#pragma unroll
    for (int i = 0; i < 32; i += 8) {
        int n = n0 + ty + i, k = k0 + tx;
        __nv_bfloat16 h, l;
        bsplit(t[tx][ty + i], h, l);
        wh[(size_t)n * QD + k] = h;
        wl[(size_t)n * QD + k] = l;
    }
}

__global__ __launch_bounds__(256) void mask_pack_kernel(const int* __restrict__ m)
{
    size_t w = (size_t)blockIdx.x * 256 + threadIdx.x;
    const int* src = m + w * 32;
    uint32_t bits = 0;
#pragma unroll
    for (int j = 0; j < 32; j++) bits |= (uint32_t)(src[j] > 0) << j;
    g_mb[w] = bits;
}

// ---------------------------------------------------------------------------
// Kernel A: QKV projection.  BM=BN=128, BK=64, 8 warps (2x4), warp 64x32.
// ---------------------------------------------------------------------------
__global__ __launch_bounds__(256, 2) void qkv_hmma()
{
    extern __shared__ __align__(16) char smem[];
    char* sAh = smem;
    char* sAl = smem + TILE_A;
    char* sBh = smem + 2 * TILE_A;
    char* sBl = smem + 3 * TILE_A;

    const int tid = threadIdx.x, lane = tid & 31, w = tid >> 5;
    const int wm0 = (w >> 2) * 64, wn0 = (w & 3) * 32;
    const int z = blockIdx.z;
    const int row0 = blockIdx.y * 128, col0 = blockIdx.x * 128;

    const __nv_bfloat16* wh = g_wth + (size_t)z * QD * INNER_;
    const __nv_bfloat16* wl = g_wtl + (size_t)z * QD * INNER_;

    const uint32_t uAh = smem_to_u32(sAh), uAl = smem_to_u32(sAl);
    const uint32_t uBh = smem_to_u32(sBh), uBl = smem_to_u32(sBl);

    float acc[4][4][4] = {};

    for (int k0 = 0; k0 < QD; k0 += 64) {
        load_chunk64<128, 128>(sAh, sAl, sBh, sBl,
                               g_xh + (size_t)row0 * QD + k0,
                               g_xl + (size_t)row0 * QD + k0,
                               wh + (size_t)col0 * QD + k0,
                               wl + (size_t)col0 * QD + k0,
                               QD, QD, tid);
        __syncthreads();
        mma_tiles<4, 4, 4, PITCH, PITCH>(acc, uAh, uAl, uBh, uBl, wm0, wn0, lane);
        __syncthreads();
    }

    if (z < 2) {
        __nv_bfloat16* dh_ = (z == 0) ? g_qh : g_kh;
        __nv_bfloat16* dl_ = (z == 0) ? g_ql : g_kl;
#pragma unroll
        for (int mi = 0; mi < 4; mi++)
#pragma unroll
            for (int h2 = 0; h2 < 2; h2++) {
                int m = row0 + wm0 + mi * 16 + (lane >> 2) + h2 * 8;
                int b = m >> 11, n = m & (N_ - 1);
#pragma unroll
                for (int ni = 0; ni < 4; ni++) {
                    int c = col0 + wn0 + ni * 8 + 2 * (lane & 3);
                    int hh = c >> 6, dd = c & 63;
                    __nv_bfloat16 h0, l0, h1, l1;
                    bsplit(acc[mi][ni][h2 * 2 + 0], h0, l0);
                    bsplit(acc[mi][ni][h2 * 2 + 1], h1, l1);
                    size_t off = ((size_t)(b * H_ + hh) * N_ + n) * DH + dd;
                    __nv_bfloat162 ph; ph.x = h0; ph.y = h1;
                    __nv_bfloat162 pl; pl.x = l0; pl.y = l1;
                    *(__nv_bfloat162*)(dh_ + off) = ph;
                    *(__nv_bfloat162*)(dl_ + off) = pl;
                }
            }
    } else {
        // V: single fp16 value, transposed [bh][d][n]
#pragma unroll
        for (int mi = 0; mi < 4; mi++)
#pragma unroll
            for (int h2 = 0; h2 < 2; h2++) {
                int m = row0 + wm0 + mi * 16 + (lane >> 2) + h2 * 8;
                int b = m >> 11, n = m & (N_ - 1);
#pragma unroll
                for (int ni = 0; ni < 4; ni++)
#pragma unroll
                    for (int c01 = 0; c01 < 2; c01++) {
                        int c = col0 + wn0 + ni * 8 + 2 * (lane & 3) + c01;
                        int hh = c >> 6, dd = c & 63;
                        size_t off = ((size_t)(b * H_ + hh) * DH + dd) * N_ + n;
                        g_vt[off] = __float2half(acc[mi][ni][h2 * 2 + c01]);
                    }
            }
    }
}

// ---------------------------------------------------------------------------
// Kernel B (fused): scores + mask + exp + PV, flash-style.
// Key-block = 64.  P and V fp16 single-limb (1-product O-MMA); S stays
// bf16 hi/lo 3-product.  2 CTAs/SM.  S warps 4x2 (32x32), O warps 4x2.
// Row sums accumulate across key blocks (no max subtraction -> no rescale).
// ---------------------------------------------------------------------------
__global__ __launch_bounds__(256, 2) void attn_fused()
{
    extern __shared__ __align__(16) char smem[];
    __shared__ float psum_s[128];

    char* sQh = smem + OFF_QH;  char* sQl = smem + OFF_QL;
    char* sKh = smem + OFF_KH;  char* sKl = smem + OFF_KL;
    char* sV  = smem + OFF_V;   char* sP  = smem + OFF_P;

    const int tid = threadIdx.x, lane = tid & 31, w = tid >> 5;
    const int wmS = (w >> 1) * 32, wnS = (w & 1) * 32;
    const int wmO = (w >> 1) * 32, wnO = (w & 1) * 32;
    const int z = blockIdx.y, b = z >> 4, hh = z & 15;
    const int row0 = blockIdx.x * 128;

    const size_t qb = (size_t)z * N_ * DH;
    const size_t vb = (size_t)z * DH * N_;

    const uint32_t uQh = smem_to_u32(sQh), uQl = smem_to_u32(sQl);
    const uint32_t uKh = smem_to_u32(sKh), uKl = smem_to_u32(sKl);
    const uint32_t uV  = smem_to_u32(sV),  uP  = smem_to_u32(sP);

    // Load Q block (128x64 hi/lo) once; batched LDG->STS.
    {
        uint4 qh[4], ql[4];
#pragma unroll
        for (int j = 0; j < 4; j++) {
            int i = tid + j * 256, r = i >> 3, c = i & 7;
            qh[j] = *((const uint4*)(g_qh + qb + (size_t)(row0 + r) * DH) + c);
            ql[j] = *((const uint4*)(g_ql + qb + (size_t)(row0 + r) * DH) + c);
        }
#pragma unroll
        for (int j = 0; j < 4; j++) {
            int i = tid + j * 256, r = i >> 3, c = i & 7;
            *(uint4*)(sQh + r * PITCH + c * 16) = qh[j];
            *(uint4*)(sQl + r * PITCH + c * 16) = ql[j];
        }
    }
    if (tid < 128) psum_s[tid] = 0.f;

    float accO[2][4][4] = {};

    for (int j = 0; j < N_ / 64; j++) {
        __syncthreads();   // prior O-mma done with K/V/P; Q+psum visible (j=0)
        load_kv64(sKh, sKl, sV,
                  g_kh + qb + (size_t)(j * 64) * DH,
                  g_kl + qb + (size_t)(j * 64) * DH,
                  g_vt + vb + j * 64,
                  tid);
        __syncthreads();   // K/V visible

        // S = Q K^T  (128x64 tile, warp 32x32)
        float accS[2][4][4] = {};
        mma_tiles<2, 4, 4, PITCH, PITCH>(accS, uQh, uQl, uKh, uKl, wmS, wnS, lane);

        // mask + exp -> P (smem, fp16) + row-sum accumulation
        const int mword = (j * 64 + wnS) >> 5;
#pragma unroll
        for (int mi = 0; mi < 2; mi++)
#pragma unroll
            for (int h2 = 0; h2 < 2; h2++) {
                int rloc = wmS + mi * 16 + (lane >> 2) + h2 * 8;
                int i = row0 + rloc;
                uint32_t mw = g_mb[((size_t)b * N_ + i) * (N_ / 32) + mword];
                float rs = 0.f;
#pragma unroll
                for (int ni = 0; ni < 4; ni++) {
                    int bit = ni * 8 + 2 * (lane & 3);
                    float e0 = 0.f, e1 = 0.f;
                    if ((mw >> bit) & 1u)
                        e0 = __expf(accS[mi][ni][h2 * 2 + 0] * 0.125f);
                    if ((mw >> (bit + 1)) & 1u)
                        e1 = __expf(accS[mi][ni][h2 * 2 + 1] * 0.125f);
                    rs += e0 + e1;
                    int col = wnS + ni * 8 + 2 * (lane & 3);
                    *(__half2*)(sP + rloc * PITCH + col * 2) =
                        __floats2half2_rn(e0, e1);
                }
                rs += __shfl_xor_sync(0xFFFFFFFF, rs, 1);
                rs += __shfl_xor_sync(0xFFFFFFFF, rs, 2);
                if ((lane & 3) == 0) atomicAdd(&psum_s[rloc], rs);
            }
        __syncthreads();   // P visible

        // O += P @ V  (fp16 single product; A = P 128x64k, B = V 64d x 64k)
#pragma unroll
        for (int ks = 0; ks < 4; ks++) {
            uint32_t ap[2][4];
#pragma unroll
            for (int mi = 0; mi < 2; mi++)
                ldm_x4<PITCH>(ap[mi], uP, wmO + mi * 16, ks * 2, lane);
#pragma unroll
            for (int nj = 0; nj < 2; nj++) {
                uint32_t bv[4];
                ldm_x4<PITCH>(bv, uV, wnO + nj * 16, ks * 2, lane);
#pragma unroll
                for (int mi = 0; mi < 2; mi++) {
                    mma_f16(accO[mi][nj * 2],     ap[mi], bv[0], bv[2]);
                    mma_f16(accO[mi][nj * 2 + 1], ap[mi], bv[1], bv[3]);
                }
            }
        }
    }
    __syncthreads();

    // Normalize by row sum and write [b*N+i][h*64+c] hi/lo
#pragma unroll
    for (int mi = 0; mi < 2; mi++)
#pragma unroll
        for (int h2 = 0; h2 < 2; h2++) {
            int rloc = wmO + mi * 16 + (lane >> 2) + h2 * 8;
            int i = row0 + rloc;
            float inv = 1.f / psum_s[rloc];
#pragma unroll
            for (int ni = 0; ni < 4; ni++) {
                int c = wnO + ni * 8 + 2 * (lane & 3);
                __nv_bfloat16 h0, l0, h1, l1;
                bsplit(accO[mi][ni][h2 * 2 + 0] * inv, h0, l0);
                bsplit(accO[mi][ni][h2 * 2 + 1] * inv, h1, l1);
                size_t off = ((size_t)(b * N_ + i)) * INNER_ + hh * 64 + c;
                __nv_bfloat162 ph; ph.x = h0; ph.y = h1;
                __nv_bfloat162 pl; pl.x = l0; pl.y = l1;
                *(__nv_bfloat162*)(g_ath + off) = ph;
                *(__nv_bfloat162*)(g_atl + off) = pl;
            }
        }
}

// ---------------------------------------------------------------------------
// Kernel C: output projection + bias -> d_out (fp32).  16 chunks of 64.
// ---------------------------------------------------------------------------
__global__ __launch_bounds__(256, 2) void outproj_hmma(
    const float* __restrict__ bo, float* __restrict__ out)
{
    extern __shared__ __align__(16) char smem[];
    char* sAh = smem;
    char* sAl = smem + TILE_A;
    char* sBh = smem + 2 * TILE_A;
    char* sBl = smem + 3 * TILE_A;

    const int tid = threadIdx.x, lane = tid & 31, w = tid >> 5;
    const int wm0 = (w >> 2) * 64, wn0 = (w & 3) * 32;
    const int row0 = blockIdx.y * 128, col0 = blockIdx.x * 128;

    const __nv_bfloat16* wh = g_wth + (size_t)3 * QD * INNER_;
    const __nv_bfloat16* wl = g_wtl + (size_t)3 * QD * INNER_;

    const uint32_t uAh = smem_to_u32(sAh), uAl = smem_to_u32(sAl);
    const uint32_t uBh = smem_to_u32(sBh), uBl = smem_to_u32(sBl);

    float acc[4][4][4] = {};

    for (int k0 = 0; k0 < INNER_; k0 += 64) {
        load_chunk64<128, 128>(sAh, sAl, sBh, sBl,
                               g_ath + (size_t)row0 * INNER_ + k0,
                               g_atl + (size_t)row0 * INNER_ + k0,
                               wh + (size_t)col0 * QD + k0,
                               wl + (size_t)col0 * QD + k0,
                               INNER_, QD, tid);
        __syncthreads();
        mma_tiles<4, 4, 4, PITCH, PITCH>(acc, uAh, uAl, uBh, uBl, wm0, wn0, lane);
        __syncthreads();
    }

#pragma unroll
    for (int mi = 0; mi < 4; mi++)
#pragma unroll
        for (int h2 = 0; h2 < 2; h2++) {
            int m = row0 + wm0 + mi * 16 + (lane >> 2) + h2 * 8;
#pragma unroll
            for (int ni = 0; ni < 4; ni++) {
                int c = col0 + wn0 + ni * 8 + 2 * (lane & 3);
                float2 o;
                o.x = acc[mi][ni][h2 * 2 + 0] + __ldg(bo + c + 0);
                o.y = acc[mi][ni][h2 * 2 + 1] + __ldg(bo + c + 1);
                *(float2*)(out + (size_t)m * QD + c) = o;
            }
        }
}

// ---------------------------------------------------------------------------
// Launch
// ---------------------------------------------------------------------------
extern "C" void kernel_launch(void* const* d_in, const int* in_sizes, int n_in,
                              void* d_out, int out_size)
{
    const float* x     = (const float*)d_in[0];
    const int*   masks = (const int*)  d_in[1];
    const float* Wq    = (const float*)d_in[2];
    const float* Wk    = (const float*)d_in[3];
    const float* Wv    = (const float*)d_in[4];
    const float* Wo    = (const float*)d_in[5];
    const float* bo    = (const float*)d_in[6];
    float* out = (float*)d_out;
    (void)in_sizes; (void)n_in; (void)out_size;

    // Idempotent, called every launch (no static guards).
    cudaFuncSetAttribute(qkv_hmma,     cudaFuncAttributeMaxDynamicSharedMemorySize, SM_BIG);
    cudaFuncSetAttribute(attn_fused,   cudaFuncAttributeMaxDynamicSharedMemorySize, SM_FUSED);
    cudaFuncSetAttribute(outproj_hmma, cudaFuncAttributeMaxDynamicSharedMemorySize, SM_BIG);

    // Preprocessing
    conv_x_kernel<<<(ROWS * QD) / (256 * 8), 256>>>(x);
    w_trans_kernel<<<dim3(32, 32, 4), dim3(32, 8)>>>(Wq, Wk, Wv, Wo);
    mask_pack_kernel<<<(B_ * N_ * (N_ / 32)) / 256, 256>>>(masks);

    // Main pipeline
    qkv_hmma<<<dim3(INNER_ / 128, ROWS / 128, 3), 256, SM_BIG>>>();
    attn_fused<<<dim3(N_ / 128, BH), 256, SM_FUSED>>>();
    outproj_hmma<<<dim3(QD / 128, ROWS / 128), 256, SM_BIG>>>(bo, out);
}